// round 1
// baseline (speedup 1.0000x reference)
#include <cuda_runtime.h>
#include <cstdint>
#include <cstddef>

// Problem constants
#define BB 4
#define TT 1024
#define CC 1024
#define HH 16
#define DH 64
#define FF 4096
#define MM (BB*TT)          // 4096 rows

// ---------------- scratch (device globals; no allocation allowed) ----------------
__device__ float g_q  [(size_t)MM*CC];
__device__ float g_k  [(size_t)MM*CC];
__device__ float g_v  [(size_t)MM*CC];
__device__ float g_s  [(size_t)BB*HH*TT*TT];   // 256 MB attention scores/probs
__device__ float g_ctx[(size_t)MM*CC];
__device__ float g_o  [(size_t)MM*CC];
__device__ float g_x1 [(size_t)MM*CC];
__device__ float g_x2 [(size_t)MM*CC];
__device__ float g_ff [(size_t)MM*FF];         // 64 MB

#define FMA16(acc,a,b) \
  acc[0][0]+=a.x*b.x; acc[0][1]+=a.x*b.y; acc[0][2]+=a.x*b.z; acc[0][3]+=a.x*b.w; \
  acc[1][0]+=a.y*b.x; acc[1][1]+=a.y*b.y; acc[1][2]+=a.y*b.z; acc[1][3]+=a.y*b.w; \
  acc[2][0]+=a.z*b.x; acc[2][1]+=a.z*b.y; acc[2][2]+=a.z*b.z; acc[2][3]+=a.z*b.w; \
  acc[3][0]+=a.w*b.x; acc[3][1]+=a.w*b.y; acc[3][2]+=a.w*b.z; acc[3][3]+=a.w*b.w;

// ---------------- generic 64x64x16 SGEMM: C = A@W (+bias) (relu) -----------------
// A row-major [*, lda], W row-major [K, ldb], C row-major [*, ldc].
// grid: (N/64, M/64). All dims multiples of 64/16 for this problem.
template<bool BIAS, bool RELU>
__global__ void __launch_bounds__(256)
gemm64(const float* __restrict__ A, const float* __restrict__ W,
       const float* __restrict__ bias, float* __restrict__ C,
       int K, int lda, int ldb, int ldc)
{
    __shared__ float As[16][68];   // transposed: As[k][m]
    __shared__ float Bs[16][68];   // Bs[k][n]
    const int tid = threadIdx.x;
    const int tx = tid & 15, ty = tid >> 4;
    const int m0 = blockIdx.y * 64, n0 = blockIdx.x * 64;
    const int ar = tid >> 2, ac = (tid & 3) << 2;
    const int br = tid >> 4, bc = (tid & 15) << 2;
    const float* Ap = A + (size_t)(m0 + ar) * lda + ac;
    const float* Wp = W + (size_t)br * ldb + n0 + bc;
    float acc[4][4] = {};
    for (int k0 = 0; k0 < K; k0 += 16) {
        float4 a4 = *(const float4*)(Ap + k0);
        As[ac + 0][ar] = a4.x; As[ac + 1][ar] = a4.y;
        As[ac + 2][ar] = a4.z; As[ac + 3][ar] = a4.w;
        *(float4*)&Bs[br][bc] = *(const float4*)(Wp + (size_t)k0 * ldb);
        __syncthreads();
#pragma unroll
        for (int kk = 0; kk < 16; kk++) {
            float4 a = *(const float4*)&As[kk][ty * 4];
            float4 b = *(const float4*)&Bs[kk][tx * 4];
            FMA16(acc, a, b);
        }
        __syncthreads();
    }
    float4 bv = make_float4(0.f, 0.f, 0.f, 0.f);
    if (BIAS) bv = *(const float4*)(bias + n0 + tx * 4);
#pragma unroll
    for (int i = 0; i < 4; i++) {
        float4 r;
        r.x = acc[i][0] + bv.x; r.y = acc[i][1] + bv.y;
        r.z = acc[i][2] + bv.z; r.w = acc[i][3] + bv.w;
        if (RELU) {
            r.x = fmaxf(r.x, 0.f); r.y = fmaxf(r.y, 0.f);
            r.z = fmaxf(r.z, 0.f); r.w = fmaxf(r.w, 0.f);
        }
        *(float4*)(C + (size_t)(m0 + ty * 4 + i) * ldc + n0 + tx * 4) = r;
    }
}

// ------------- scores: S[z,q,k] = (Q_h[q,:] . K_h[k,:]) / 8, batched over z=b*H+h --
// grid: (T/64 k-tiles, T/64 q-tiles, B*H). Causal blocks fully above diagonal skipped.
template<bool CAUSAL>
__global__ void __launch_bounds__(256)
scores64(const float* __restrict__ Q, const float* __restrict__ K,
         float* __restrict__ S)
{
    if (CAUSAL && blockIdx.x > blockIdx.y) return;   // whole tile masked
    const int z = blockIdx.z;
    const int b = z >> 4, h = z & 15;
    const int q0 = blockIdx.y * 64, k0 = blockIdx.x * 64;
    __shared__ float Qs[64][68];   // transposed: Qs[c][q]
    __shared__ float Ks[64][68];   // transposed: Ks[c][k]
    const int tid = threadIdx.x;
    const int r = tid >> 4, c4 = (tid & 15) << 2;
    const float* Qp = Q + ((size_t)b * TT + q0 + r) * CC + h * DH + c4;
    const float* Kp = K + ((size_t)b * TT + k0 + r) * CC + h * DH + c4;
#pragma unroll
    for (int i = 0; i < 4; i++) {
        float4 qv = *(const float4*)(Qp + (size_t)i * 16 * CC);
        Qs[c4 + 0][r + i * 16] = qv.x; Qs[c4 + 1][r + i * 16] = qv.y;
        Qs[c4 + 2][r + i * 16] = qv.z; Qs[c4 + 3][r + i * 16] = qv.w;
        float4 kv = *(const float4*)(Kp + (size_t)i * 16 * CC);
        Ks[c4 + 0][r + i * 16] = kv.x; Ks[c4 + 1][r + i * 16] = kv.y;
        Ks[c4 + 2][r + i * 16] = kv.z; Ks[c4 + 3][r + i * 16] = kv.w;
    }
    __syncthreads();
    const int tx = tid & 15, ty = tid >> 4;
    float acc[4][4] = {};
#pragma unroll 16
    for (int c = 0; c < 64; c++) {
        float4 a = *(const float4*)&Qs[c][ty * 4];
        float4 b2 = *(const float4*)&Ks[c][tx * 4];
        FMA16(acc, a, b2);
    }
    float* Sp = S + ((size_t)z * TT + q0 + ty * 4) * TT + k0 + tx * 4;
#pragma unroll
    for (int i = 0; i < 4; i++) {
        float4 r4;
        r4.x = acc[i][0] * 0.125f; r4.y = acc[i][1] * 0.125f;
        r4.z = acc[i][2] * 0.125f; r4.w = acc[i][3] * 0.125f;
        *(float4*)(Sp + (size_t)i * TT) = r4;
    }
}

// ---------------- softmax (in place), one block per (b,h,q) row ----------------
__device__ __forceinline__ float warpMax(float v) {
#pragma unroll
    for (int o = 16; o; o >>= 1) v = fmaxf(v, __shfl_xor_sync(0xffffffffu, v, o));
    return v;
}
__device__ __forceinline__ float warpSum(float v) {
#pragma unroll
    for (int o = 16; o; o >>= 1) v += __shfl_xor_sync(0xffffffffu, v, o);
    return v;
}

template<bool CAUSAL>
__global__ void __launch_bounds__(256)
softmax_k(float* __restrict__ S, const unsigned char* __restrict__ pad)
{
    const size_t rid = blockIdx.x;
    const int q = (int)(rid & (TT - 1));
    const int z = (int)(rid >> 10);
    const int b = z >> 4;
    float* row = S + rid * (size_t)TT;
    const int tid = threadIdx.x;
    const int col = tid * 4;

    float4 v = *(const float4*)(row + col);
    const uchar4 p = *(const uchar4*)(pad + (size_t)b * TT + col);
    if (p.x || (CAUSAL && col + 0 > q)) v.x = -INFINITY;
    if (p.y || (CAUSAL && col + 1 > q)) v.y = -INFINITY;
    if (p.z || (CAUSAL && col + 2 > q)) v.z = -INFINITY;
    if (p.w || (CAUSAL && col + 3 > q)) v.w = -INFINITY;

    __shared__ float shm[8], shs[8];
    float mx = fmaxf(fmaxf(v.x, v.y), fmaxf(v.z, v.w));
    mx = warpMax(mx);
    if ((tid & 31) == 0) shm[tid >> 5] = mx;
    __syncthreads();
    mx = fmaxf(fmaxf(fmaxf(shm[0], shm[1]), fmaxf(shm[2], shm[3])),
               fmaxf(fmaxf(shm[4], shm[5]), fmaxf(shm[6], shm[7])));

    float4 e;
    e.x = __expf(v.x - mx) ; e.x = expf(v.x - mx);
    e.y = expf(v.y - mx);
    e.z = expf(v.z - mx);
    e.w = expf(v.w - mx);
    float s = e.x + e.y + e.z + e.w;
    s = warpSum(s);
    if ((tid & 31) == 0) shs[tid >> 5] = s;
    __syncthreads();
    s = (shs[0] + shs[1]) + (shs[2] + shs[3]) + (shs[4] + shs[5]) + (shs[6] + shs[7]);
    const float inv = 1.0f / s;
    e.x *= inv; e.y *= inv; e.z *= inv; e.w *= inv;
    *(float4*)(row + col) = e;
}

// ---------------- AV: ctx[b,q,h,:] = sum_k P[z,q,k] * V[b,k,h,:] ----------------
// grid: (T/64 q-tiles, B*H)
__global__ void __launch_bounds__(256)
av64(const float* __restrict__ P, const float* __restrict__ V,
     float* __restrict__ OutC)
{
    const int z = blockIdx.y;
    const int b = z >> 4, h = z & 15;
    const float* A = P + (size_t)z * TT * TT;                 // lda = TT
    const float* W = V + (size_t)b * TT * CC + h * DH;        // ldb = CC
    float* Cc = OutC + (size_t)b * TT * CC + h * DH;          // ldc = CC
    const int m0 = blockIdx.x * 64;

    __shared__ float As[16][68];
    __shared__ float Bs[16][68];
    const int tid = threadIdx.x;
    const int tx = tid & 15, ty = tid >> 4;
    const int ar = tid >> 2, ac = (tid & 3) << 2;
    const int br = tid >> 4, bc = (tid & 15) << 2;
    const float* Ap = A + (size_t)(m0 + ar) * TT + ac;
    const float* Wp = W + (size_t)br * CC + bc;
    float acc[4][4] = {};
    for (int k0 = 0; k0 < TT; k0 += 16) {
        float4 a4 = *(const float4*)(Ap + k0);
        As[ac + 0][ar] = a4.x; As[ac + 1][ar] = a4.y;
        As[ac + 2][ar] = a4.z; As[ac + 3][ar] = a4.w;
        *(float4*)&Bs[br][bc] = *(const float4*)(Wp + (size_t)k0 * CC);
        __syncthreads();
#pragma unroll
        for (int kk = 0; kk < 16; kk++) {
            float4 a = *(const float4*)&As[kk][ty * 4];
            float4 b2 = *(const float4*)&Bs[kk][tx * 4];
            FMA16(acc, a, b2);
        }
        __syncthreads();
    }
#pragma unroll
    for (int i = 0; i < 4; i++) {
        float4 r;
        r.x = acc[i][0]; r.y = acc[i][1]; r.z = acc[i][2]; r.w = acc[i][3];
        *(float4*)(Cc + (size_t)(m0 + ty * 4 + i) * CC + tx * 4) = r;
    }
}

// ---------------- fused residual-add + LayerNorm, one block per row --------------
__global__ void __launch_bounds__(256)
add_ln(const float* __restrict__ X, const float* __restrict__ R,
       const float* __restrict__ g, const float* __restrict__ be,
       float* __restrict__ out)
{
    const size_t row = blockIdx.x;
    const int tid = threadIdx.x;
    const int col = tid * 4;
    float4 xv = *(const float4*)(X + row * CC + col);
    float4 rv = *(const float4*)(R + row * CC + col);
    float4 v;
    v.x = xv.x + rv.x; v.y = xv.y + rv.y; v.z = xv.z + rv.z; v.w = xv.w + rv.w;

    __shared__ float sh1[8], sh2[8];
    float s = (v.x + v.y) + (v.z + v.w);
    float sq = v.x * v.x + v.y * v.y + v.z * v.z + v.w * v.w;
    s = warpSum(s); sq = warpSum(sq);
    if ((tid & 31) == 0) { sh1[tid >> 5] = s; sh2[tid >> 5] = sq; }
    __syncthreads();
    s  = (sh1[0] + sh1[1]) + (sh1[2] + sh1[3]) + (sh1[4] + sh1[5]) + (sh1[6] + sh1[7]);
    sq = (sh2[0] + sh2[1]) + (sh2[2] + sh2[3]) + (sh2[4] + sh2[5]) + (sh2[6] + sh2[7]);
    const float mean = s * (1.0f / CC);
    const float var = sq * (1.0f / CC) - mean * mean;
    const float rstd = rsqrtf(var + 1e-5f);

    float4 gg = *(const float4*)(g + col);
    float4 bb = *(const float4*)(be + col);
    float4 o;
    o.x = (v.x - mean) * rstd * gg.x + bb.x;
    o.y = (v.y - mean) * rstd * gg.y + bb.y;
    o.z = (v.z - mean) * rstd * gg.z + bb.z;
    o.w = (v.w - mean) * rstd * gg.w + bb.w;
    *(float4*)(out + row * CC + col) = o;
}

// ------------------------------- launcher ---------------------------------------
extern "C" void kernel_launch(void* const* d_in, const int* in_sizes, int n_in,
                              void* d_out, int out_size)
{
    const float* x    = (const float*)d_in[0];
    const float* enc  = (const float*)d_in[1];
    const unsigned char* tmask = (const unsigned char*)d_in[2];
    const unsigned char* smask = (const unsigned char*)d_in[3];
    const float* Wq1 = (const float*)d_in[4];
    const float* Wk1 = (const float*)d_in[5];
    const float* Wv1 = (const float*)d_in[6];
    const float* Wo1 = (const float*)d_in[7];
    const float* ln1g = (const float*)d_in[8];
    const float* ln1b = (const float*)d_in[9];
    const float* Wq2 = (const float*)d_in[10];
    const float* Wk2 = (const float*)d_in[11];
    const float* Wv2 = (const float*)d_in[12];
    const float* Wo2 = (const float*)d_in[13];
    const float* ln2g = (const float*)d_in[14];
    const float* ln2b = (const float*)d_in[15];
    const float* Wf1 = (const float*)d_in[16];
    const float* bf1 = (const float*)d_in[17];
    const float* Wf2 = (const float*)d_in[18];
    const float* bf2 = (const float*)d_in[19];
    const float* ln3g = (const float*)d_in[20];
    const float* ln3b = (const float*)d_in[21];
    float* out = (float*)d_out;

    float *gq, *gk, *gv, *gs, *gctx, *go, *gx1, *gx2, *gff;
    cudaGetSymbolAddress((void**)&gq,  g_q);
    cudaGetSymbolAddress((void**)&gk,  g_k);
    cudaGetSymbolAddress((void**)&gv,  g_v);
    cudaGetSymbolAddress((void**)&gs,  g_s);
    cudaGetSymbolAddress((void**)&gctx, g_ctx);
    cudaGetSymbolAddress((void**)&go,  g_o);
    cudaGetSymbolAddress((void**)&gx1, g_x1);
    cudaGetSymbolAddress((void**)&gx2, g_x2);
    cudaGetSymbolAddress((void**)&gff, g_ff);

    const dim3 blk(256);
    const dim3 gProj(CC / 64, MM / 64);        // 16 x 64
    const dim3 gF1(FF / 64, MM / 64);          // 64 x 64
    const dim3 gS(TT / 64, TT / 64, BB * HH);  // 16 x 16 x 64
    const dim3 gAV(TT / 64, BB * HH);          // 16 x 64
    const int nSm = BB * HH * TT;              // 65536 softmax rows
    const int nLn = MM;                        // 4096 rows

    // ---- self-attention (causal) ----
    gemm64<false, false><<<gProj, blk>>>(x, Wq1, nullptr, gq, CC, CC, CC, CC);
    gemm64<false, false><<<gProj, blk>>>(x, Wk1, nullptr, gk, CC, CC, CC, CC);
    gemm64<false, false><<<gProj, blk>>>(x, Wv1, nullptr, gv, CC, CC, CC, CC);
    scores64<true><<<gS, blk>>>(gq, gk, gs);
    softmax_k<true><<<nSm, blk>>>(gs, tmask);
    av64<<<gAV, blk>>>(gs, gv, gctx);
    gemm64<false, false><<<gProj, blk>>>(gctx, Wo1, nullptr, go, CC, CC, CC, CC);
    add_ln<<<nLn, blk>>>(x, go, ln1g, ln1b, gx1);

    // ---- cross-attention ----
    gemm64<false, false><<<gProj, blk>>>(gx1, Wq2, nullptr, gq, CC, CC, CC, CC);
    gemm64<false, false><<<gProj, blk>>>(enc, Wk2, nullptr, gk, CC, CC, CC, CC);
    gemm64<false, false><<<gProj, blk>>>(enc, Wv2, nullptr, gv, CC, CC, CC, CC);
    scores64<false><<<gS, blk>>>(gq, gk, gs);
    softmax_k<false><<<nSm, blk>>>(gs, smask);
    av64<<<gAV, blk>>>(gs, gv, gctx);
    gemm64<false, false><<<gProj, blk>>>(gctx, Wo2, nullptr, go, CC, CC, CC, CC);
    add_ln<<<nLn, blk>>>(gx1, go, ln2g, ln2b, gx2);

    // ---- FFN ----
    gemm64<true, true ><<<gF1,  blk>>>(gx2, Wf1, bf1, gff, CC, CC, FF, FF);
    gemm64<true, false><<<gProj, blk>>>(gff, Wf2, bf2, go, FF, FF, CC, CC);
    add_ln<<<nLn, blk>>>(gx2, go, ln3g, ln3b, out);
}

// round 3
// speedup vs baseline: 2.0228x; 2.0228x over previous
#include <cuda_runtime.h>
#include <cstdint>
#include <cstddef>

// Problem constants
#define BB 4
#define TT 1024
#define CC 1024
#define HH 16
#define DH 64
#define FF 4096
#define MM (BB*TT)          // 4096 rows

// ---------------- scratch (device globals; no allocation allowed) ----------------
__device__ float g_q  [(size_t)MM*CC];
__device__ float g_k  [(size_t)MM*CC];
__device__ float g_v  [(size_t)MM*CC];
__device__ float g_vt [(size_t)MM*CC];         // V transposed per batch: [B][C][T]
__device__ float g_s  [(size_t)BB*HH*TT*TT];   // 256 MB attention scores/probs
__device__ float g_ctx[(size_t)MM*CC];
__device__ float g_o  [(size_t)MM*CC];
__device__ float g_x1 [(size_t)MM*CC];
__device__ float g_x2 [(size_t)MM*CC];
__device__ float g_ff [(size_t)MM*FF];         // 64 MB
// transposed weights: 8 x [1024x1024] + Wf1^T [4096x1024] + Wf2^T [1024x4096]
__device__ float g_wt [8u*1024u*1024u + 2u*4096u*1024u];

// ============================ small helpers ======================================
__device__ __forceinline__ float to_tf32(float x) {
    uint32_t o;
    asm("cvt.rna.tf32.f32 %0, %1;" : "=r"(o) : "r"(__float_as_uint(x)));
    return __uint_as_float(o);
}
__device__ __forceinline__ void mma_tf32(float* d, const float* a, const float* b) {
    asm volatile(
        "mma.sync.aligned.m16n8k8.row.col.f32.tf32.tf32.f32 "
        "{%0,%1,%2,%3},{%4,%5,%6,%7},{%8,%9},{%0,%1,%2,%3};"
        : "+f"(d[0]), "+f"(d[1]), "+f"(d[2]), "+f"(d[3])
        : "r"(__float_as_uint(a[0])), "r"(__float_as_uint(a[1])),
          "r"(__float_as_uint(a[2])), "r"(__float_as_uint(a[3])),
          "r"(__float_as_uint(b[0])), "r"(__float_as_uint(b[1])));
}

// ====================== 32x32 tiled transpose (batched in z) =====================
__global__ void __launch_bounds__(256)
transpose_k(const float* __restrict__ in, float* __restrict__ out, int R, int C)
{
    in  += (size_t)blockIdx.z * R * C;
    out += (size_t)blockIdx.z * R * C;
    __shared__ float t[32][33];
    const int bx = blockIdx.x * 32, by = blockIdx.y * 32;
    int x = bx + threadIdx.x;
#pragma unroll
    for (int i = 0; i < 32; i += 8)
        t[threadIdx.y + i][threadIdx.x] = in[(size_t)(by + threadIdx.y + i) * C + x];
    __syncthreads();
    x = by + threadIdx.x;
#pragma unroll
    for (int i = 0; i < 32; i += 8)
        out[(size_t)(bx + threadIdx.y + i) * R + x] = t[threadIdx.x][threadIdx.y + i];
}

// ================= tf32 mma.sync GEMM: C[M,N] = A[M,K] @ Bt[N,K]^T ===============
// A row-major [*, lda] (K contiguous), Bt row-major [*, ldb] (K contiguous).
// Block tile 128 x TN, 8 warps arranged WR x WC, K staged 32, double buffered.
// z-batch: offsets decomposed as z=(zb*16+zh): ptr += zb*s?B + zh*s?H.
template<int TN, int WR, int WC, bool BIAS, bool RELU, bool CSKIP>
__global__ void __launch_bounds__(256, 1)
gemm_mma(const float* __restrict__ A, const float* __restrict__ Bt,
         const float* __restrict__ bias, float* __restrict__ C,
         int K, int lda, int ldb, int ldc, float scale,
         long long saB, long long saH, long long sbB, long long sbH,
         long long scB, long long scH)
{
    constexpr int TM  = 128;
    constexpr int WM  = TM / WR;        // 64 or 32
    constexpr int WN  = TN / WC;        // 32
    constexpr int MI  = WM / 16;        // 4 or 2
    constexpr int NI  = WN / 8;         // 4
    constexpr int LDP = 36;             // padded stage row (floats)
    constexpr int BTPR = 256 / TN;      // threads per B stage row (2 or 4)
    constexpr int BLD  = 8 / BTPR;      // float4 per thread for B stage (4 or 2)

    extern __shared__ float smf[];
    float* sA = smf;                    // [2][128][36]
    float* sB = smf + 2 * TM * LDP;     // [2][TN ][36]

    const int bxn = blockIdx.x * TN, bym = blockIdx.y * TM;
    if (CSKIP && bxn > bym + TM - 1) return;   // tile fully above causal diagonal

    const int z = blockIdx.z, zb = z >> 4, zh = z & 15;
    A   += (long long)zb * saB + (long long)zh * saH;
    Bt  += (long long)zb * sbB + (long long)zh * sbH;
    C   += (long long)zb * scB + (long long)zh * scH;

    const int tid = threadIdx.x, wid = tid >> 5, lane = tid & 31;
    const int wr = wid / WC, wc = wid % WC;
    const int g = lane >> 2, qc = lane & 3;

    // stage loaders
    const int am  = tid >> 1,  acb = (tid & 1) * 16;            // A: 128 rows x 32
    const int bn  = tid / BTPR, bcb = (tid % BTPR) * (32 / BTPR); // B: TN rows x 32
    const float* Ag = A  + (long long)(bym + am) * lda + acb;
    const float* Bg = Bt + (long long)(bxn + bn) * ldb + bcb;

    float acc[MI][NI][4];
#pragma unroll
    for (int i = 0; i < MI; i++)
#pragma unroll
        for (int j = 0; j < NI; j++)
#pragma unroll
            for (int r = 0; r < 4; r++) acc[i][j][r] = 0.f;

    float4 pa[4], pb[BLD];
#pragma unroll
    for (int j = 0; j < 4; j++)   pa[j] = *(const float4*)(Ag + j * 4);
#pragma unroll
    for (int j = 0; j < BLD; j++) pb[j] = *(const float4*)(Bg + j * 4);
    {
        float* aw = sA;  float* bw = sB;
#pragma unroll
        for (int j = 0; j < 4; j++) {
            float4 v = pa[j];
            v.x = to_tf32(v.x); v.y = to_tf32(v.y); v.z = to_tf32(v.z); v.w = to_tf32(v.w);
            *(float4*)(aw + am * LDP + acb + j * 4) = v;
        }
#pragma unroll
        for (int j = 0; j < BLD; j++) {
            float4 v = pb[j];
            v.x = to_tf32(v.x); v.y = to_tf32(v.y); v.z = to_tf32(v.z); v.w = to_tf32(v.w);
            *(float4*)(bw + bn * LDP + bcb + j * 4) = v;
        }
    }
    __syncthreads();

    const int nst = K >> 5;
    for (int it = 0; it < nst; ++it) {
        const int buf = it & 1;
        if (it + 1 < nst) {
            const int k0 = (it + 1) * 32;
#pragma unroll
            for (int j = 0; j < 4; j++)   pa[j] = *(const float4*)(Ag + k0 + j * 4);
#pragma unroll
            for (int j = 0; j < BLD; j++) pb[j] = *(const float4*)(Bg + k0 + j * 4);
        }
        const float* a_s = sA + buf * TM * LDP + (wr * WM + g) * LDP;
        const float* b_s = sB + buf * TN * LDP + (wc * WN + g) * LDP;
#pragma unroll
        for (int ks = 0; ks < 4; ks++) {
            float av_[MI][4], bv_[NI][2];
#pragma unroll
            for (int mi = 0; mi < MI; mi++) {
                const float* p = a_s + mi * 16 * LDP + ks * 8 + qc;
                av_[mi][0] = p[0];
                av_[mi][1] = p[8 * LDP];
                av_[mi][2] = p[4];
                av_[mi][3] = p[8 * LDP + 4];
            }
#pragma unroll
            for (int ni = 0; ni < NI; ni++) {
                const float* p = b_s + ni * 8 * LDP + ks * 8 + qc;
                bv_[ni][0] = p[0];
                bv_[ni][1] = p[4];
            }
#pragma unroll
            for (int mi = 0; mi < MI; mi++)
#pragma unroll
                for (int ni = 0; ni < NI; ni++)
                    mma_tf32(acc[mi][ni], av_[mi], bv_[ni]);
        }
        if (it + 1 < nst) {
            float* aw = sA + ((it + 1) & 1) * TM * LDP;
            float* bw = sB + ((it + 1) & 1) * TN * LDP;
#pragma unroll
            for (int j = 0; j < 4; j++) {
                float4 v = pa[j];
                v.x = to_tf32(v.x); v.y = to_tf32(v.y); v.z = to_tf32(v.z); v.w = to_tf32(v.w);
                *(float4*)(aw + am * LDP + acb + j * 4) = v;
            }
#pragma unroll
            for (int j = 0; j < BLD; j++) {
                float4 v = pb[j];
                v.x = to_tf32(v.x); v.y = to_tf32(v.y); v.z = to_tf32(v.z); v.w = to_tf32(v.w);
                *(float4*)(bw + bn * LDP + bcb + j * 4) = v;
            }
            __syncthreads();
        }
    }

    // epilogue: c0,c1 -> (row, col..col+1); c2,c3 -> (row+8, ...)
#pragma unroll
    for (int mi = 0; mi < MI; mi++) {
        const int row = bym + wr * WM + mi * 16 + g;
#pragma unroll
        for (int ni = 0; ni < NI; ni++) {
            const int col = bxn + wc * WN + ni * 8 + qc * 2;
            float2 bv = make_float2(0.f, 0.f);
            if (BIAS) bv = *(const float2*)(bias + col);
            float2 v0, v1;
            v0.x = acc[mi][ni][0] * scale + bv.x;
            v0.y = acc[mi][ni][1] * scale + bv.y;
            v1.x = acc[mi][ni][2] * scale + bv.x;
            v1.y = acc[mi][ni][3] * scale + bv.y;
            if (RELU) {
                v0.x = fmaxf(v0.x, 0.f); v0.y = fmaxf(v0.y, 0.f);
                v1.x = fmaxf(v1.x, 0.f); v1.y = fmaxf(v1.y, 0.f);
            }
            *(float2*)(C + (long long)row * ldc + col)       = v0;
            *(float2*)(C + (long long)(row + 8) * ldc + col) = v1;
        }
    }
}

// ============================ softmax / layernorm ================================
__device__ __forceinline__ float warpMax(float v) {
#pragma unroll
    for (int o = 16; o; o >>= 1) v = fmaxf(v, __shfl_xor_sync(0xffffffffu, v, o));
    return v;
}
__device__ __forceinline__ float warpSum(float v) {
#pragma unroll
    for (int o = 16; o; o >>= 1) v += __shfl_xor_sync(0xffffffffu, v, o);
    return v;
}

template<bool CAUSAL>
__global__ void __launch_bounds__(256)
softmax_k(float* __restrict__ S, const unsigned char* __restrict__ pad)
{
    const size_t rid = blockIdx.x;
    const int q = (int)(rid & (TT - 1));
    const int z = (int)(rid >> 10);
    const int b = z >> 4;
    float* row = S + rid * (size_t)TT;
    const int tid = threadIdx.x;
    const int col = tid * 4;

    float4 v = *(const float4*)(row + col);
    const uchar4 p = *(const uchar4*)(pad + (size_t)b * TT + col);
    if (p.x || (CAUSAL && col + 0 > q)) v.x = -INFINITY;
    if (p.y || (CAUSAL && col + 1 > q)) v.y = -INFINITY;
    if (p.z || (CAUSAL && col + 2 > q)) v.z = -INFINITY;
    if (p.w || (CAUSAL && col + 3 > q)) v.w = -INFINITY;

    __shared__ float shm[8], shs[8];
    float mx = fmaxf(fmaxf(v.x, v.y), fmaxf(v.z, v.w));
    mx = warpMax(mx);
    if ((tid & 31) == 0) shm[tid >> 5] = mx;
    __syncthreads();
    mx = fmaxf(fmaxf(fmaxf(shm[0], shm[1]), fmaxf(shm[2], shm[3])),
               fmaxf(fmaxf(shm[4], shm[5]), fmaxf(shm[6], shm[7])));

    float4 e;
    e.x = expf(v.x - mx);
    e.y = expf(v.y - mx);
    e.z = expf(v.z - mx);
    e.w = expf(v.w - mx);
    float s = e.x + e.y + e.z + e.w;
    s = warpSum(s);
    if ((tid & 31) == 0) shs[tid >> 5] = s;
    __syncthreads();
    s = (shs[0] + shs[1]) + (shs[2] + shs[3]) + (shs[4] + shs[5]) + (shs[6] + shs[7]);
    const float inv = 1.0f / s;
    e.x *= inv; e.y *= inv; e.z *= inv; e.w *= inv;
    *(float4*)(row + col) = e;
}

__global__ void __launch_bounds__(256)
add_ln(const float* __restrict__ X, const float* __restrict__ R,
       const float* __restrict__ g, const float* __restrict__ be,
       float* __restrict__ out)
{
    const size_t row = blockIdx.x;
    const int tid = threadIdx.x;
    const int col = tid * 4;
    float4 xv = *(const float4*)(X + row * CC + col);
    float4 rv = *(const float4*)(R + row * CC + col);
    float4 v;
    v.x = xv.x + rv.x; v.y = xv.y + rv.y; v.z = xv.z + rv.z; v.w = xv.w + rv.w;

    __shared__ float sh1[8], sh2[8];
    float s = (v.x + v.y) + (v.z + v.w);
    float sq = v.x * v.x + v.y * v.y + v.z * v.z + v.w * v.w;
    s = warpSum(s); sq = warpSum(sq);
    if ((tid & 31) == 0) { sh1[tid >> 5] = s; sh2[tid >> 5] = sq; }
    __syncthreads();
    s  = (sh1[0] + sh1[1]) + (sh1[2] + sh1[3]) + (sh1[4] + sh1[5]) + (sh1[6] + sh1[7]);
    sq = (sh2[0] + sh2[1]) + (sh2[2] + sh2[3]) + (sh2[4] + sh2[5]) + (sh2[6] + sh2[7]);
    const float mean = s * (1.0f / CC);
    const float var = sq * (1.0f / CC) - mean * mean;
    const float rstd = rsqrtf(var + 1e-5f);

    float4 gg = *(const float4*)(g + col);
    float4 bb = *(const float4*)(be + col);
    float4 o;
    o.x = (v.x - mean) * rstd * gg.x + bb.x;
    o.y = (v.y - mean) * rstd * gg.y + bb.y;
    o.z = (v.z - mean) * rstd * gg.z + bb.z;
    o.w = (v.w - mean) * rstd * gg.w + bb.w;
    *(float4*)(out + row * CC + col) = o;
}

// ------------------------------- launcher ---------------------------------------
extern "C" void kernel_launch(void* const* d_in, const int* in_sizes, int n_in,
                              void* d_out, int out_size)
{
    const float* x    = (const float*)d_in[0];
    const float* enc  = (const float*)d_in[1];
    const unsigned char* tmask = (const unsigned char*)d_in[2];
    const unsigned char* smask = (const unsigned char*)d_in[3];
    const float* Wq1 = (const float*)d_in[4];
    const float* Wk1 = (const float*)d_in[5];
    const float* Wv1 = (const float*)d_in[6];
    const float* Wo1 = (const float*)d_in[7];
    const float* ln1g = (const float*)d_in[8];
    const float* ln1b = (const float*)d_in[9];
    const float* Wq2 = (const float*)d_in[10];
    const float* Wk2 = (const float*)d_in[11];
    const float* Wv2 = (const float*)d_in[12];
    const float* Wo2 = (const float*)d_in[13];
    const float* ln2g = (const float*)d_in[14];
    const float* ln2b = (const float*)d_in[15];
    const float* Wf1 = (const float*)d_in[16];
    const float* bf1 = (const float*)d_in[17];
    const float* Wf2 = (const float*)d_in[18];
    const float* bf2 = (const float*)d_in[19];
    const float* ln3g = (const float*)d_in[20];
    const float* ln3b = (const float*)d_in[21];
    float* out = (float*)d_out;

    float *gq, *gk, *gv, *gvt, *gs, *gctx, *go, *gx1, *gx2, *gff, *gwt;
    cudaGetSymbolAddress((void**)&gq,  g_q);
    cudaGetSymbolAddress((void**)&gk,  g_k);
    cudaGetSymbolAddress((void**)&gv,  g_v);
    cudaGetSymbolAddress((void**)&gvt, g_vt);
    cudaGetSymbolAddress((void**)&gs,  g_s);
    cudaGetSymbolAddress((void**)&gctx, g_ctx);
    cudaGetSymbolAddress((void**)&go,  g_o);
    cudaGetSymbolAddress((void**)&gx1, g_x1);
    cudaGetSymbolAddress((void**)&gx2, g_x2);
    cudaGetSymbolAddress((void**)&gff, g_ff);
    cudaGetSymbolAddress((void**)&gwt, g_wt);

    float* tq1 = gwt + 0u * 1048576u;
    float* tk1 = gwt + 1u * 1048576u;
    float* tv1 = gwt + 2u * 1048576u;
    float* to1 = gwt + 3u * 1048576u;
    float* tq2 = gwt + 4u * 1048576u;
    float* tk2 = gwt + 5u * 1048576u;
    float* tv2 = gwt + 6u * 1048576u;
    float* to2 = gwt + 7u * 1048576u;
    float* tf1 = gwt + 8u * 1048576u;               // [F, C]
    float* tf2 = gwt + 8u * 1048576u + 4194304u;    // [C, F]

    // dynamic smem sizes
    const int SM128 = 2 * (128 + 128) * 36 * 4;   // 73728
    const int SM64  = 2 * (128 + 64)  * 36 * 4;   // 55296

    auto* kProj  = gemm_mma<128, 2, 4, false, false, false>;
    auto* kFfn1  = gemm_mma<128, 2, 4, true,  true,  false>;
    auto* kFfn2  = gemm_mma<128, 2, 4, true,  false, false>;
    auto* kScoC  = gemm_mma<128, 2, 4, false, false, true >;
    auto* kScoF  = gemm_mma<128, 2, 4, false, false, false>;
    auto* kAv    = gemm_mma<64,  4, 2, false, false, false>;
    cudaFuncSetAttribute(kProj, cudaFuncAttributeMaxDynamicSharedMemorySize, SM128);
    cudaFuncSetAttribute(kFfn1, cudaFuncAttributeMaxDynamicSharedMemorySize, SM128);
    cudaFuncSetAttribute(kFfn2, cudaFuncAttributeMaxDynamicSharedMemorySize, SM128);
    cudaFuncSetAttribute(kScoC, cudaFuncAttributeMaxDynamicSharedMemorySize, SM128);
    cudaFuncSetAttribute(kAv,   cudaFuncAttributeMaxDynamicSharedMemorySize, SM64);

    const dim3 blk(256);
    const dim3 tblk(32, 8);

    // ---- weight transposes (K-major B operands) ----
    transpose_k<<<dim3(CC/32, CC/32), tblk>>>(Wq1, tq1, CC, CC);
    transpose_k<<<dim3(CC/32, CC/32), tblk>>>(Wk1, tk1, CC, CC);
    transpose_k<<<dim3(CC/32, CC/32), tblk>>>(Wv1, tv1, CC, CC);
    transpose_k<<<dim3(CC/32, CC/32), tblk>>>(Wo1, to1, CC, CC);
    transpose_k<<<dim3(CC/32, CC/32), tblk>>>(Wq2, tq2, CC, CC);
    transpose_k<<<dim3(CC/32, CC/32), tblk>>>(Wk2, tk2, CC, CC);
    transpose_k<<<dim3(CC/32, CC/32), tblk>>>(Wv2, tv2, CC, CC);
    transpose_k<<<dim3(CC/32, CC/32), tblk>>>(Wo2, to2, CC, CC);
    transpose_k<<<dim3(FF/32, CC/32), tblk>>>(Wf1, tf1, CC, FF);
    transpose_k<<<dim3(CC/32, FF/32), tblk>>>(Wf2, tf2, FF, CC);

    const dim3 gP(CC/128, MM/128, 1);       // (8, 32)
    const dim3 gF1(FF/128, MM/128, 1);      // (32, 32)
    const dim3 gF2(CC/128, MM/128, 1);      // (8, 32)
    const dim3 gSc(TT/128, TT/128, BB*HH);  // (8, 8, 64)
    const dim3 gAv(1, TT/128, BB*HH);       // (1, 8, 64)
    const dim3 gVt(CC/32, TT/32, BB);
    const int nSm = BB * HH * TT;
    const int nLn = MM;

    const long long ZA = (long long)TT * CC;   // batch stride in activations
    const long long ZS = (long long)TT * TT;   // per-head score stride

    // ---- self-attention (causal) ----
    kProj<<<gP, blk, SM128>>>(x, tq1, nullptr, gq, CC, CC, CC, CC, 1.f, 0,0,0,0,0,0);
    kProj<<<gP, blk, SM128>>>(x, tk1, nullptr, gk, CC, CC, CC, CC, 1.f, 0,0,0,0,0,0);
    kProj<<<gP, blk, SM128>>>(x, tv1, nullptr, gv, CC, CC, CC, CC, 1.f, 0,0,0,0,0,0);
    transpose_k<<<gVt, tblk>>>(gv, gvt, TT, CC);
    kScoC<<<gSc, blk, SM128>>>(gq, gk, nullptr, gs, DH, CC, CC, TT, 0.125f,
                               ZA, 64, ZA, 64, 16*ZS, ZS);
    softmax_k<true><<<nSm, blk>>>(gs, tmask);
    kAv<<<gAv, blk, SM64>>>(gs, gvt, nullptr, gctx, TT, TT, TT, CC, 1.f,
                            16*ZS, ZS, (long long)CC*TT, 64LL*TT, ZA, 64);
    kProj<<<gP, blk, SM128>>>(gctx, to1, nullptr, go, CC, CC, CC, CC, 1.f, 0,0,0,0,0,0);
    add_ln<<<nLn, blk>>>(x, go, ln1g, ln1b, gx1);

    // ---- cross-attention ----
    kProj<<<gP, blk, SM128>>>(gx1, tq2, nullptr, gq, CC, CC, CC, CC, 1.f, 0,0,0,0,0,0);
    kProj<<<gP, blk, SM128>>>(enc, tk2, nullptr, gk, CC, CC, CC, CC, 1.f, 0,0,0,0,0,0);
    kProj<<<gP, blk, SM128>>>(enc, tv2, nullptr, gv, CC, CC, CC, CC, 1.f, 0,0,0,0,0,0);
    transpose_k<<<gVt, tblk>>>(gv, gvt, TT, CC);
    kScoF<<<gSc, blk, SM128>>>(gq, gk, nullptr, gs, DH, CC, CC, TT, 0.125f,
                               ZA, 64, ZA, 64, 16*ZS, ZS);
    softmax_k<false><<<nSm, blk>>>(gs, smask);
    kAv<<<gAv, blk, SM64>>>(gs, gvt, nullptr, gctx, TT, TT, TT, CC, 1.f,
                            16*ZS, ZS, (long long)CC*TT, 64LL*TT, ZA, 64);
    kProj<<<gP, blk, SM128>>>(gctx, to2, nullptr, go, CC, CC, CC, CC, 1.f, 0,0,0,0,0,0);
    add_ln<<<nLn, blk>>>(gx1, go, ln2g, ln2b, gx2);

    // ---- FFN ----
    kFfn1<<<gF1, blk, SM128>>>(gx2, tf1, bf1, gff, CC, CC, CC, FF, 1.f, 0,0,0,0,0,0);
    kFfn2<<<gF2, blk, SM128>>>(gff, tf2, bf2, go, FF, FF, FF, CC, 1.f, 0,0,0,0,0,0);
    add_ln<<<nLn, blk>>>(gx2, go, ln3g, ln3b, out);
}

// round 4
// speedup vs baseline: 2.3394x; 1.1565x over previous
#include <cuda_runtime.h>
#include <cstdint>
#include <cstddef>

// Problem constants
#define BB 4
#define TT 1024
#define CC 1024
#define HH 16
#define DH 64
#define FF 4096
#define MM (BB*TT)          // 4096 rows

// ---------------- scratch (device globals; no allocation allowed) ----------------
__device__ float g_q  [(size_t)MM*CC];
__device__ float g_k  [(size_t)MM*CC];
__device__ float g_v  [(size_t)MM*CC];
__device__ float g_vt [(size_t)MM*CC];         // V transposed per batch: [B][C][T]
__device__ float g_ctx[(size_t)MM*CC];
__device__ float g_o  [(size_t)MM*CC];
__device__ float g_x1 [(size_t)MM*CC];
__device__ float g_x2 [(size_t)MM*CC];
__device__ float g_ff [(size_t)MM*FF];         // 64 MB
// transposed weights: 8 x [1024x1024] + Wf1^T [4096x1024] + Wf2^T [1024x4096]
__device__ float g_wt [8u*1024u*1024u + 2u*4096u*1024u];

// ============================ small helpers ======================================
__device__ __forceinline__ float to_tf32(float x) {
    uint32_t o;
    asm("cvt.rna.tf32.f32 %0, %1;" : "=r"(o) : "r"(__float_as_uint(x)));
    return __uint_as_float(o);
}
__device__ __forceinline__ void mma_tf32(float* d, const float* a, const float* b) {
    asm volatile(
        "mma.sync.aligned.m16n8k8.row.col.f32.tf32.tf32.f32 "
        "{%0,%1,%2,%3},{%4,%5,%6,%7},{%8,%9},{%0,%1,%2,%3};"
        : "+f"(d[0]), "+f"(d[1]), "+f"(d[2]), "+f"(d[3])
        : "r"(__float_as_uint(a[0])), "r"(__float_as_uint(a[1])),
          "r"(__float_as_uint(a[2])), "r"(__float_as_uint(a[3])),
          "r"(__float_as_uint(b[0])), "r"(__float_as_uint(b[1])));
}
__device__ __forceinline__ uint32_t smem_u32(const void* p) {
    uint32_t a;
    asm("{ .reg .u64 t; cvta.to.shared.u64 t, %1; cvt.u32.u64 %0, t; }" : "=r"(a) : "l"(p));
    return a;
}
__device__ __forceinline__ void cp16(uint32_t dst, const void* src) {
    asm volatile("cp.async.cg.shared.global [%0], [%1], 16;" :: "r"(dst), "l"(src));
}

// ====================== 32x32 tiled transpose (batched in z) =====================
__global__ void __launch_bounds__(256)
transpose_k(const float* __restrict__ in, float* __restrict__ out, int R, int C)
{
    in  += (size_t)blockIdx.z * R * C;
    out += (size_t)blockIdx.z * R * C;
    __shared__ float t[32][33];
    const int bx = blockIdx.x * 32, by = blockIdx.y * 32;
    int x = bx + threadIdx.x;
#pragma unroll
    for (int i = 0; i < 32; i += 8)
        t[threadIdx.y + i][threadIdx.x] = in[(size_t)(by + threadIdx.y + i) * C + x];
    __syncthreads();
    x = by + threadIdx.x;
#pragma unroll
    for (int i = 0; i < 32; i += 8)
        out[(size_t)(bx + threadIdx.y + i) * R + x] = t[threadIdx.x][threadIdx.y + i];
}

// ================= tf32 mma.sync GEMM: C[M,N] = A[M,K] @ Bt[N,K]^T ===============
template<int TN, int WR, int WC, bool BIAS, bool RELU>
__global__ void __launch_bounds__(256, 1)
gemm_mma(const float* __restrict__ A, const float* __restrict__ Bt,
         const float* __restrict__ bias, float* __restrict__ C,
         int K, int lda, int ldb, int ldc, float scale)
{
    constexpr int TM  = 128;
    constexpr int WM  = TM / WR;
    constexpr int WN  = TN / WC;
    constexpr int MI  = WM / 16;
    constexpr int NI  = WN / 8;
    constexpr int LDP = 36;
    constexpr int BTPR = 256 / TN;
    constexpr int BLD  = 8 / BTPR;

    extern __shared__ float smf[];
    float* sA = smf;
    float* sB = smf + 2 * TM * LDP;

    const int bxn = blockIdx.x * TN, bym = blockIdx.y * TM;
    const int tid = threadIdx.x, wid = tid >> 5, lane = tid & 31;
    const int wr = wid / WC, wc = wid % WC;
    const int g = lane >> 2, qc = lane & 3;

    const int am  = tid >> 1,  acb = (tid & 1) * 16;
    const int bn  = tid / BTPR, bcb = (tid % BTPR) * (32 / BTPR);
    const float* Ag = A  + (long long)(bym + am) * lda + acb;
    const float* Bg = Bt + (long long)(bxn + bn) * ldb + bcb;

    float acc[MI][NI][4];
#pragma unroll
    for (int i = 0; i < MI; i++)
#pragma unroll
        for (int j = 0; j < NI; j++)
#pragma unroll
            for (int r = 0; r < 4; r++) acc[i][j][r] = 0.f;

    float4 pa[4], pb[BLD];
#pragma unroll
    for (int j = 0; j < 4; j++)   pa[j] = *(const float4*)(Ag + j * 4);
#pragma unroll
    for (int j = 0; j < BLD; j++) pb[j] = *(const float4*)(Bg + j * 4);
    {
        float* aw = sA;  float* bw = sB;
#pragma unroll
        for (int j = 0; j < 4; j++) {
            float4 v = pa[j];
            v.x = to_tf32(v.x); v.y = to_tf32(v.y); v.z = to_tf32(v.z); v.w = to_tf32(v.w);
            *(float4*)(aw + am * LDP + acb + j * 4) = v;
        }
#pragma unroll
        for (int j = 0; j < BLD; j++) {
            float4 v = pb[j];
            v.x = to_tf32(v.x); v.y = to_tf32(v.y); v.z = to_tf32(v.z); v.w = to_tf32(v.w);
            *(float4*)(bw + bn * LDP + bcb + j * 4) = v;
        }
    }
    __syncthreads();

    const int nst = K >> 5;
    for (int it = 0; it < nst; ++it) {
        const int buf = it & 1;
        if (it + 1 < nst) {
            const int k0 = (it + 1) * 32;
#pragma unroll
            for (int j = 0; j < 4; j++)   pa[j] = *(const float4*)(Ag + k0 + j * 4);
#pragma unroll
            for (int j = 0; j < BLD; j++) pb[j] = *(const float4*)(Bg + k0 + j * 4);
        }
        const float* a_s = sA + buf * TM * LDP + (wr * WM + g) * LDP;
        const float* b_s = sB + buf * TN * LDP + (wc * WN + g) * LDP;
#pragma unroll
        for (int ks = 0; ks < 4; ks++) {
            float av_[MI][4], bv_[NI][2];
#pragma unroll
            for (int mi = 0; mi < MI; mi++) {
                const float* p = a_s + mi * 16 * LDP + ks * 8 + qc;
                av_[mi][0] = p[0];
                av_[mi][1] = p[8 * LDP];
                av_[mi][2] = p[4];
                av_[mi][3] = p[8 * LDP + 4];
            }
#pragma unroll
            for (int ni = 0; ni < NI; ni++) {
                const float* p = b_s + ni * 8 * LDP + ks * 8 + qc;
                bv_[ni][0] = p[0];
                bv_[ni][1] = p[4];
            }
#pragma unroll
            for (int mi = 0; mi < MI; mi++)
#pragma unroll
                for (int ni = 0; ni < NI; ni++)
                    mma_tf32(acc[mi][ni], av_[mi], bv_[ni]);
        }
        if (it + 1 < nst) {
            float* aw = sA + ((it + 1) & 1) * TM * LDP;
            float* bw = sB + ((it + 1) & 1) * TN * LDP;
#pragma unroll
            for (int j = 0; j < 4; j++) {
                float4 v = pa[j];
                v.x = to_tf32(v.x); v.y = to_tf32(v.y); v.z = to_tf32(v.z); v.w = to_tf32(v.w);
                *(float4*)(aw + am * LDP + acb + j * 4) = v;
            }
#pragma unroll
            for (int j = 0; j < BLD; j++) {
                float4 v = pb[j];
                v.x = to_tf32(v.x); v.y = to_tf32(v.y); v.z = to_tf32(v.z); v.w = to_tf32(v.w);
                *(float4*)(bw + bn * LDP + bcb + j * 4) = v;
            }
            __syncthreads();
        }
    }

#pragma unroll
    for (int mi = 0; mi < MI; mi++) {
        const int row = bym + wr * WM + mi * 16 + g;
#pragma unroll
        for (int ni = 0; ni < NI; ni++) {
            const int col = bxn + wc * WN + ni * 8 + qc * 2;
            float2 bv = make_float2(0.f, 0.f);
            if (BIAS) bv = *(const float2*)(bias + col);
            float2 v0, v1;
            v0.x = acc[mi][ni][0] * scale + bv.x;
            v0.y = acc[mi][ni][1] * scale + bv.y;
            v1.x = acc[mi][ni][2] * scale + bv.x;
            v1.y = acc[mi][ni][3] * scale + bv.y;
            if (RELU) {
                v0.x = fmaxf(v0.x, 0.f); v0.y = fmaxf(v0.y, 0.f);
                v1.x = fmaxf(v1.x, 0.f); v1.y = fmaxf(v1.y, 0.f);
            }
            *(float2*)(C + (long long)row * ldc + col)       = v0;
            *(float2*)(C + (long long)(row + 8) * ldc + col) = v1;
        }
    }
}

// ====================== flash attention (tf32 mma, online softmax) ===============
// grid: (q-tiles=8, B*H=64). 256 threads = 8 warps, warp w owns 16 q-rows.
// smem: Q[128][68] | K[2][128][68] | Vt[2][64][132] | mask[2][32 u32] | flags[2]
#define FL_SQ  0
#define FL_SK  8704           // floats
#define FL_SV  26112
#define FL_MSK 43008
#define FSMEM  ((43008 + 66) * 4)

template<bool CAUSAL>
__global__ void __launch_bounds__(256, 1)
flash_k(const float* __restrict__ Qg, const float* __restrict__ Kg,
        const float* __restrict__ Vg, const unsigned char* __restrict__ padg,
        float* __restrict__ Og)
{
    extern __shared__ float sm[];
    const int tid = threadIdx.x, lane = tid & 31, w = tid >> 5;
    const int g = lane >> 2, qc = lane & 3;
    const int qt = blockIdx.x;
    const int z = blockIdx.y, b = z >> 4, h = z & 15;

    const float* Qp = Qg + (size_t)b * TT * CC + h * 64;
    const float* Kp = Kg + (size_t)b * TT * CC + h * 64;
    const float* Vp = Vg + ((size_t)b * CC + h * 64) * TT;
    const unsigned char* padp = padg + (size_t)b * TT;
    float* Op = Og + (size_t)b * TT * CC + h * 64;

    const uint32_t sQa = smem_u32(sm);
    const uint32_t sKa = sQa + FL_SK * 4;
    const uint32_t sVa = sQa + FL_SV * 4;
    uint32_t* sMskp = (uint32_t*)(sm + FL_MSK);

    const int nkt = CAUSAL ? qt + 1 : (TT / 128);

    // prologue: Q tile + tile 0 (K/V/mask) into cp.async group 0
    {
        const float* qs = Qp + (size_t)(qt * 128 + (tid >> 1)) * CC + (tid & 1) * 32;
        uint32_t qd = sQa + (tid >> 1) * 272 + (tid & 1) * 128;
#pragma unroll
        for (int j = 0; j < 8; j++) cp16(qd + j * 16, qs + j * 4);
    }
    auto issue_kv = [&](int kt, int buf) {
        const float* ks = Kp + (size_t)(kt * 128 + (tid >> 1)) * CC + (tid & 1) * 32;
        uint32_t kd = sKa + buf * 34816u + (tid >> 1) * 272 + (tid & 1) * 128;
#pragma unroll
        for (int j = 0; j < 8; j++) cp16(kd + j * 16, ks + j * 4);
        const float* vs = Vp + (size_t)(tid >> 2) * TT + kt * 128 + (tid & 3) * 32;
        uint32_t vd = sVa + buf * 33792u + (tid >> 2) * 528 + (tid & 3) * 128;
#pragma unroll
        for (int j = 0; j < 8; j++) cp16(vd + j * 16, vs + j * 4);
        if (tid < 32) {
            uint32_t mv = *(const uint32_t*)(padp + (size_t)kt * 128 + tid * 4);
            sMskp[buf * 32 + tid] = mv;
            uint32_t f = __reduce_or_sync(0xffffffffu, mv);
            if (tid == 0) sMskp[64 + buf] = f;
        }
    };
    issue_kv(0, 0);
    asm volatile("cp.async.commit_group;" ::: "memory");

    float m0 = -INFINITY, m1 = -INFINITY, l0 = 0.f, l1 = 0.f;
    float oacc[8][4];
#pragma unroll
    for (int j = 0; j < 8; j++)
#pragma unroll
        for (int r = 0; r < 4; r++) oacc[j][r] = 0.f;

    const int r0 = w * 16 + g, r1 = r0 + 8;
    const int s0l = (lane & ~3) | (qc >> 1), s1l = s0l + 2;
    const bool odd = (qc & 1) != 0;

    for (int kt = 0; kt < nkt; ++kt) {
        const int buf = kt & 1;
        if (kt + 1 < nkt) {
            issue_kv(kt + 1, buf ^ 1);
            asm volatile("cp.async.commit_group;" ::: "memory");
            asm volatile("cp.async.wait_group 1;" ::: "memory");
        } else {
            asm volatile("cp.async.wait_group 0;" ::: "memory");
        }
        __syncthreads();

        // ---- S = Q @ K^T (warp: 16 x 128) ----
        float aq[8][4];
        {
            const float* qr = sm + (size_t)(w * 16 + g) * 68;
#pragma unroll
            for (int ks = 0; ks < 8; ks++) {
                aq[ks][0] = qr[ks * 8 + qc];
                aq[ks][1] = qr[8 * 68 + ks * 8 + qc];
                aq[ks][2] = qr[ks * 8 + qc + 4];
                aq[ks][3] = qr[8 * 68 + ks * 8 + qc + 4];
            }
        }
        float sacc[16][4];
#pragma unroll
        for (int ni = 0; ni < 16; ni++)
#pragma unroll
            for (int r = 0; r < 4; r++) sacc[ni][r] = 0.f;
        {
            const float* kb = sm + FL_SK + buf * 8704;
#pragma unroll
            for (int ks = 0; ks < 8; ks++)
#pragma unroll
                for (int ni = 0; ni < 16; ni++) {
                    const float* kr = kb + (ni * 8 + g) * 68 + ks * 8;
                    float bv[2] = { kr[qc], kr[qc + 4] };
                    mma_tf32(sacc[ni], aq[ks], bv);
                }
        }

        // ---- scale + masks + row stats ----
        const uint32_t pf = sMskp[64 + buf];
        const unsigned char* mb = (const unsigned char*)(sMskp + buf * 32);
        float tm0 = -INFINITY, tm1 = -INFINITY;
#pragma unroll
        for (int ni = 0; ni < 16; ni++) {
            float s0 = sacc[ni][0] * 0.125f, s1 = sacc[ni][1] * 0.125f;
            float s2 = sacc[ni][2] * 0.125f, s3 = sacc[ni][3] * 0.125f;
            const int c0 = ni * 8 + qc * 2;
            if (CAUSAL && kt == qt) {
                if (c0     > r0) s0 = -INFINITY;
                if (c0 + 1 > r0) s1 = -INFINITY;
                if (c0     > r1) s2 = -INFINITY;
                if (c0 + 1 > r1) s3 = -INFINITY;
            }
            if (pf) {
                if (mb[c0])     { s0 = -INFINITY; s2 = -INFINITY; }
                if (mb[c0 + 1]) { s1 = -INFINITY; s3 = -INFINITY; }
            }
            sacc[ni][0] = s0; sacc[ni][1] = s1; sacc[ni][2] = s2; sacc[ni][3] = s3;
            tm0 = fmaxf(tm0, fmaxf(s0, s1));
            tm1 = fmaxf(tm1, fmaxf(s2, s3));
        }
        tm0 = fmaxf(tm0, __shfl_xor_sync(0xffffffffu, tm0, 1));
        tm0 = fmaxf(tm0, __shfl_xor_sync(0xffffffffu, tm0, 2));
        tm1 = fmaxf(tm1, __shfl_xor_sync(0xffffffffu, tm1, 1));
        tm1 = fmaxf(tm1, __shfl_xor_sync(0xffffffffu, tm1, 2));
        const float mn0 = fmaxf(m0, tm0), mn1 = fmaxf(m1, tm1);

        float sum0 = 0.f, sum1 = 0.f;
#pragma unroll
        for (int ni = 0; ni < 16; ni++) {
            float p0 = __expf(sacc[ni][0] - mn0);
            float p1 = __expf(sacc[ni][1] - mn0);
            float p2 = __expf(sacc[ni][2] - mn1);
            float p3 = __expf(sacc[ni][3] - mn1);
            sacc[ni][0] = p0; sacc[ni][1] = p1; sacc[ni][2] = p2; sacc[ni][3] = p3;
            sum0 += p0 + p1; sum1 += p2 + p3;
        }
        sum0 += __shfl_xor_sync(0xffffffffu, sum0, 1);
        sum0 += __shfl_xor_sync(0xffffffffu, sum0, 2);
        sum1 += __shfl_xor_sync(0xffffffffu, sum1, 1);
        sum1 += __shfl_xor_sync(0xffffffffu, sum1, 2);

        const float sc0 = __expf(m0 - mn0), sc1 = __expf(m1 - mn1);
        l0 = l0 * sc0 + sum0;  l1 = l1 * sc1 + sum1;
        m0 = mn0;  m1 = mn1;
#pragma unroll
        for (int nj = 0; nj < 8; nj++) {
            oacc[nj][0] *= sc0; oacc[nj][1] *= sc0;
            oacc[nj][2] *= sc1; oacc[nj][3] *= sc1;
        }

        // ---- O += P @ V (P A-frags via in-register shfl permute) ----
        {
            const float* vb = sm + FL_SV + buf * 8448;
#pragma unroll
            for (int k2 = 0; k2 < 16; k2++) {
                float v00 = __shfl_sync(0xffffffffu, sacc[k2][0], s0l);
                float v01 = __shfl_sync(0xffffffffu, sacc[k2][1], s0l);
                float v20 = __shfl_sync(0xffffffffu, sacc[k2][2], s0l);
                float v21 = __shfl_sync(0xffffffffu, sacc[k2][3], s0l);
                float w00 = __shfl_sync(0xffffffffu, sacc[k2][0], s1l);
                float w01 = __shfl_sync(0xffffffffu, sacc[k2][1], s1l);
                float w20 = __shfl_sync(0xffffffffu, sacc[k2][2], s1l);
                float w21 = __shfl_sync(0xffffffffu, sacc[k2][3], s1l);
                float pa[4];
                pa[0] = to_tf32(odd ? v01 : v00);
                pa[1] = to_tf32(odd ? v21 : v20);
                pa[2] = to_tf32(odd ? w01 : w00);
                pa[3] = to_tf32(odd ? w21 : w20);
#pragma unroll
                for (int nj = 0; nj < 8; nj++) {
                    const float* vr = vb + (nj * 8 + g) * 132 + k2 * 8;
                    float bv[2] = { vr[qc], vr[qc + 4] };
                    mma_tf32(oacc[nj], pa, bv);
                }
            }
        }
        __syncthreads();
    }

    const float inv0 = 1.f / l0, inv1 = 1.f / l1;
    float* orow0 = Op + (size_t)(qt * 128 + r0) * CC;
    float* orow1 = orow0 + 8 * CC;
#pragma unroll
    for (int nj = 0; nj < 8; nj++) {
        *(float2*)(orow0 + nj * 8 + qc * 2) =
            make_float2(oacc[nj][0] * inv0, oacc[nj][1] * inv0);
        *(float2*)(orow1 + nj * 8 + qc * 2) =
            make_float2(oacc[nj][2] * inv1, oacc[nj][3] * inv1);
    }
}

// ============================ layernorm ==========================================
__device__ __forceinline__ float warpSum(float v) {
#pragma unroll
    for (int o = 16; o; o >>= 1) v += __shfl_xor_sync(0xffffffffu, v, o);
    return v;
}

__global__ void __launch_bounds__(256)
add_ln(const float* __restrict__ X, const float* __restrict__ R,
       const float* __restrict__ g, const float* __restrict__ be,
       float* __restrict__ out)
{
    const size_t row = blockIdx.x;
    const int tid = threadIdx.x;
    const int col = tid * 4;
    float4 xv = *(const float4*)(X + row * CC + col);
    float4 rv = *(const float4*)(R + row * CC + col);
    float4 v;
    v.x = xv.x + rv.x; v.y = xv.y + rv.y; v.z = xv.z + rv.z; v.w = xv.w + rv.w;

    __shared__ float sh1[8], sh2[8];
    float s = (v.x + v.y) + (v.z + v.w);
    float sq = v.x * v.x + v.y * v.y + v.z * v.z + v.w * v.w;
    s = warpSum(s); sq = warpSum(sq);
    if ((tid & 31) == 0) { sh1[tid >> 5] = s; sh2[tid >> 5] = sq; }
    __syncthreads();
    s  = (sh1[0] + sh1[1]) + (sh1[2] + sh1[3]) + (sh1[4] + sh1[5]) + (sh1[6] + sh1[7]);
    sq = (sh2[0] + sh2[1]) + (sh2[2] + sh2[3]) + (sh2[4] + sh2[5]) + (sh2[6] + sh2[7]);
    const float mean = s * (1.0f / CC);
    const float var = sq * (1.0f / CC) - mean * mean;
    const float rstd = rsqrtf(var + 1e-5f);

    float4 gg = *(const float4*)(g + col);
    float4 bb = *(const float4*)(be + col);
    float4 o;
    o.x = (v.x - mean) * rstd * gg.x + bb.x;
    o.y = (v.y - mean) * rstd * gg.y + bb.y;
    o.z = (v.z - mean) * rstd * gg.z + bb.z;
    o.w = (v.w - mean) * rstd * gg.w + bb.w;
    *(float4*)(out + row * CC + col) = o;
}

// ------------------------------- launcher ---------------------------------------
extern "C" void kernel_launch(void* const* d_in, const int* in_sizes, int n_in,
                              void* d_out, int out_size)
{
    const float* x    = (const float*)d_in[0];
    const float* enc  = (const float*)d_in[1];
    const unsigned char* tmask = (const unsigned char*)d_in[2];
    const unsigned char* smask = (const unsigned char*)d_in[3];
    const float* Wq1 = (const float*)d_in[4];
    const float* Wk1 = (const float*)d_in[5];
    const float* Wv1 = (const float*)d_in[6];
    const float* Wo1 = (const float*)d_in[7];
    const float* ln1g = (const float*)d_in[8];
    const float* ln1b = (const float*)d_in[9];
    const float* Wq2 = (const float*)d_in[10];
    const float* Wk2 = (const float*)d_in[11];
    const float* Wv2 = (const float*)d_in[12];
    const float* Wo2 = (const float*)d_in[13];
    const float* ln2g = (const float*)d_in[14];
    const float* ln2b = (const float*)d_in[15];
    const float* Wf1 = (const float*)d_in[16];
    const float* bf1 = (const float*)d_in[17];
    const float* Wf2 = (const float*)d_in[18];
    const float* bf2 = (const float*)d_in[19];
    const float* ln3g = (const float*)d_in[20];
    const float* ln3b = (const float*)d_in[21];
    float* out = (float*)d_out;

    float *gq, *gk, *gv, *gvt, *gctx, *go, *gx1, *gx2, *gff, *gwt;
    cudaGetSymbolAddress((void**)&gq,  g_q);
    cudaGetSymbolAddress((void**)&gk,  g_k);
    cudaGetSymbolAddress((void**)&gv,  g_v);
    cudaGetSymbolAddress((void**)&gvt, g_vt);
    cudaGetSymbolAddress((void**)&gctx, g_ctx);
    cudaGetSymbolAddress((void**)&go,  g_o);
    cudaGetSymbolAddress((void**)&gx1, g_x1);
    cudaGetSymbolAddress((void**)&gx2, g_x2);
    cudaGetSymbolAddress((void**)&gff, g_ff);
    cudaGetSymbolAddress((void**)&gwt, g_wt);

    float* tq1 = gwt + 0u * 1048576u;
    float* tk1 = gwt + 1u * 1048576u;
    float* tv1 = gwt + 2u * 1048576u;
    float* to1 = gwt + 3u * 1048576u;
    float* tq2 = gwt + 4u * 1048576u;
    float* tk2 = gwt + 5u * 1048576u;
    float* tv2 = gwt + 6u * 1048576u;
    float* to2 = gwt + 7u * 1048576u;
    float* tf1 = gwt + 8u * 1048576u;               // [F, C]
    float* tf2 = gwt + 8u * 1048576u + 4194304u;    // [C, F]

    const int SM128 = 2 * (128 + 128) * 36 * 4;   // 73728

    auto* kProj  = gemm_mma<128, 2, 4, false, false>;
    auto* kFfn1  = gemm_mma<128, 2, 4, true,  true >;
    auto* kFfn2  = gemm_mma<128, 2, 4, true,  false>;
    cudaFuncSetAttribute(kProj, cudaFuncAttributeMaxDynamicSharedMemorySize, SM128);
    cudaFuncSetAttribute(kFfn1, cudaFuncAttributeMaxDynamicSharedMemorySize, SM128);
    cudaFuncSetAttribute(kFfn2, cudaFuncAttributeMaxDynamicSharedMemorySize, SM128);
    cudaFuncSetAttribute(flash_k<true>,  cudaFuncAttributeMaxDynamicSharedMemorySize, FSMEM);
    cudaFuncSetAttribute(flash_k<false>, cudaFuncAttributeMaxDynamicSharedMemorySize, FSMEM);

    const dim3 blk(256);
    const dim3 tblk(32, 8);

    // ---- weight transposes (K-major B operands) ----
    transpose_k<<<dim3(CC/32, CC/32), tblk>>>(Wq1, tq1, CC, CC);
    transpose_k<<<dim3(CC/32, CC/32), tblk>>>(Wk1, tk1, CC, CC);
    transpose_k<<<dim3(CC/32, CC/32), tblk>>>(Wv1, tv1, CC, CC);
    transpose_k<<<dim3(CC/32, CC/32), tblk>>>(Wo1, to1, CC, CC);
    transpose_k<<<dim3(CC/32, CC/32), tblk>>>(Wq2, tq2, CC, CC);
    transpose_k<<<dim3(CC/32, CC/32), tblk>>>(Wk2, tk2, CC, CC);
    transpose_k<<<dim3(CC/32, CC/32), tblk>>>(Wv2, tv2, CC, CC);
    transpose_k<<<dim3(CC/32, CC/32), tblk>>>(Wo2, to2, CC, CC);
    transpose_k<<<dim3(FF/32, CC/32), tblk>>>(Wf1, tf1, CC, FF);
    transpose_k<<<dim3(CC/32, FF/32), tblk>>>(Wf2, tf2, FF, CC);

    const dim3 gP(CC/128, MM/128);       // (8, 32)
    const dim3 gF1(FF/128, MM/128);      // (32, 32)
    const dim3 gF2(CC/128, MM/128);      // (8, 32)
    const dim3 gFl(TT/128, BB*HH);       // (8, 64)
    const dim3 gVt(CC/32, TT/32, BB);
    const int nLn = MM;

    // ---- self-attention (causal) ----
    kProj<<<gP, blk, SM128>>>(x, tq1, nullptr, gq, CC, CC, CC, CC, 1.f);
    kProj<<<gP, blk, SM128>>>(x, tk1, nullptr, gk, CC, CC, CC, CC, 1.f);
    kProj<<<gP, blk, SM128>>>(x, tv1, nullptr, gv, CC, CC, CC, CC, 1.f);
    transpose_k<<<gVt, tblk>>>(gv, gvt, TT, CC);
    flash_k<true><<<gFl, blk, FSMEM>>>(gq, gk, gvt, tmask, gctx);
    kProj<<<gP, blk, SM128>>>(gctx, to1, nullptr, go, CC, CC, CC, CC, 1.f);
    add_ln<<<nLn, blk>>>(x, go, ln1g, ln1b, gx1);

    // ---- cross-attention ----
    kProj<<<gP, blk, SM128>>>(gx1, tq2, nullptr, gq, CC, CC, CC, CC, 1.f);
    kProj<<<gP, blk, SM128>>>(enc, tk2, nullptr, gk, CC, CC, CC, CC, 1.f);
    kProj<<<gP, blk, SM128>>>(enc, tv2, nullptr, gv, CC, CC, CC, CC, 1.f);
    transpose_k<<<gVt, tblk>>>(gv, gvt, TT, CC);
    flash_k<false><<<gFl, blk, FSMEM>>>(gq, gk, gvt, smask, gctx);
    kProj<<<gP, blk, SM128>>>(gctx, to2, nullptr, go, CC, CC, CC, CC, 1.f);
    add_ln<<<nLn, blk>>>(gx1, go, ln2g, ln2b, gx2);

    // ---- FFN ----
    kFfn1<<<gF1, blk, SM128>>>(gx2, tf1, bf1, gff, CC, CC, CC, FF, 1.f);
    kFfn2<<<gF2, blk, SM128>>>(gff, tf2, bf2, go, FF, FF, FF, CC, 1.f);
    add_ln<<<nLn, blk>>>(gx2, go, ln3g, ln3b, out);
}

// round 5
// speedup vs baseline: 2.6589x; 1.1366x over previous
#include <cuda_runtime.h>
#include <cstdint>
#include <cstddef>

// Problem constants
#define BB 4
#define TT 1024
#define CC 1024
#define HH 16
#define DH 64
#define FF 4096
#define MM (BB*TT)          // 4096 rows

// ---------------- scratch (device globals; no allocation allowed) ----------------
__device__ float g_q  [(size_t)MM*CC];
__device__ float g_vt [(size_t)MM*CC];         // V transposed per batch: [B][C][T]
__device__ float g_ctx[(size_t)MM*CC];
__device__ float g_o  [(size_t)MM*CC];
__device__ float g_x1 [(size_t)MM*CC];
__device__ float g_x2 [(size_t)MM*CC];
__device__ float g_ff [(size_t)MM*FF];         // 64 MB (also holds fused QKV / KV)
// transposed weights: 8 x [1024x1024] + Wf1^T [4096x1024] + Wf2^T [1024x4096]
__device__ float g_wt [8u*1024u*1024u + 2u*4096u*1024u];

// ============================ small helpers ======================================
__device__ __forceinline__ float to_tf32(float x) {
    uint32_t o;
    asm("cvt.rna.tf32.f32 %0, %1;" : "=r"(o) : "r"(__float_as_uint(x)));
    return __uint_as_float(o);
}
__device__ __forceinline__ void mma_tf32(float* d, const float* a, const float* b) {
    asm volatile(
        "mma.sync.aligned.m16n8k8.row.col.f32.tf32.tf32.f32 "
        "{%0,%1,%2,%3},{%4,%5,%6,%7},{%8,%9},{%0,%1,%2,%3};"
        : "+f"(d[0]), "+f"(d[1]), "+f"(d[2]), "+f"(d[3])
        : "r"(__float_as_uint(a[0])), "r"(__float_as_uint(a[1])),
          "r"(__float_as_uint(a[2])), "r"(__float_as_uint(a[3])),
          "r"(__float_as_uint(b[0])), "r"(__float_as_uint(b[1])));
}
__device__ __forceinline__ uint32_t smem_u32(const void* p) {
    uint32_t a;
    asm("{ .reg .u64 t; cvta.to.shared.u64 t, %1; cvt.u32.u64 %0, t; }" : "=r"(a) : "l"(p));
    return a;
}
__device__ __forceinline__ void cp16(uint32_t dst, const void* src) {
    asm volatile("cp.async.cg.shared.global [%0], [%1], 16;" :: "r"(dst), "l"(src));
}

// ====================== 32x32 tiled transposes ===================================
__global__ void __launch_bounds__(256)
transpose_k(const float* __restrict__ in, float* __restrict__ out, int R, int C)
{
    __shared__ float t[32][33];
    const int bx = blockIdx.x * 32, by = blockIdx.y * 32;
    int x = bx + threadIdx.x;
#pragma unroll
    for (int i = 0; i < 32; i += 8)
        t[threadIdx.y + i][threadIdx.x] = in[(size_t)(by + threadIdx.y + i) * C + x];
    __syncthreads();
    x = by + threadIdx.x;
#pragma unroll
    for (int i = 0; i < 32; i += 8)
        out[(size_t)(bx + threadIdx.y + i) * R + x] = t[threadIdx.x][threadIdx.y + i];
}

// extract + transpose V block out of a packed [B*T, ldin] buffer -> [B][C][T]
__global__ void __launch_bounds__(256)
transpose_v(const float* __restrict__ in, float* __restrict__ out, int ldin)
{
    in  += (size_t)blockIdx.z * TT * ldin;
    out += (size_t)blockIdx.z * CC * TT;
    __shared__ float t[32][33];
    const int bx = blockIdx.x * 32, by = blockIdx.y * 32;   // bx: C dim, by: T dim
#pragma unroll
    for (int i = 0; i < 32; i += 8)
        t[threadIdx.y + i][threadIdx.x] =
            in[(size_t)(by + threadIdx.y + i) * ldin + bx + threadIdx.x];
    __syncthreads();
#pragma unroll
    for (int i = 0; i < 32; i += 8)
        out[(size_t)(bx + threadIdx.y + i) * TT + by + threadIdx.x] =
            t[threadIdx.x][threadIdx.y + i];
}

// ================= tf32 mma.sync GEMM: C[M,N] = A[M,K] @ Bt[N,K]^T ===============
// cp.async 3-stage pipeline, 128x128 tile, 8 warps (2x4), 2 CTAs/SM.
#define G_LDP 36
#define G_STG (256 * G_LDP)                 // floats per stage (A128 + B128 rows)
#define GSMEM (3 * G_STG * 4)               // 110592 bytes

template<bool BIAS, bool RELU>
__global__ void __launch_bounds__(256, 2)
gemm_mma(const float* __restrict__ A, const float* __restrict__ Bt,
         const float* __restrict__ bias, float* __restrict__ C,
         int K, int lda, int ldb, int ldc)
{
    extern __shared__ float smf[];
    const int bxn = blockIdx.x * 128, bym = blockIdx.y * 128;
    const int tid = threadIdx.x, wid = tid >> 5, lane = tid & 31;
    const int wr = wid >> 2, wc = wid & 3;      // 2 x 4 warps
    const int g = lane >> 2, qc = lane & 3;

    const int row = tid >> 1, colb = (tid & 1) * 16;
    const float* Ag = A  + (size_t)(bym + row) * lda + colb;
    const float* Bg = Bt + (size_t)(bxn + row) * ldb + colb;
    const uint32_t adst = smem_u32(smf) + (uint32_t)(row * G_LDP + colb) * 4;
    const uint32_t bdst = adst + 128 * G_LDP * 4;

    float acc[4][4][4];
#pragma unroll
    for (int i = 0; i < 4; i++)
#pragma unroll
        for (int j = 0; j < 4; j++)
#pragma unroll
            for (int r = 0; r < 4; r++) acc[i][j][r] = 0.f;

    const int nst = K >> 5;

    // prologue: stages 0, 1
#pragma unroll
    for (int s = 0; s < 2; s++) {
        const float* as = Ag + s * 32;
        const float* bs = Bg + s * 32;
        const uint32_t ad = adst + s * G_STG * 4;
        const uint32_t bd = bdst + s * G_STG * 4;
#pragma unroll
        for (int j = 0; j < 4; j++) {
            cp16(ad + j * 16, as + j * 4);
            cp16(bd + j * 16, bs + j * 4);
        }
        asm volatile("cp.async.commit_group;" ::: "memory");
    }

    int buf = 0, nxt = 2;      // nxt = (it+2) % 3
    for (int it = 0; it < nst; ++it) {
        asm volatile("cp.async.wait_group 1;" ::: "memory");
        __syncthreads();
        const float* a_s = smf + buf * G_STG + (wr * 64 + g) * G_LDP;
        const float* b_s = smf + buf * G_STG + 128 * G_LDP + (wc * 32 + g) * G_LDP;
#pragma unroll
        for (int ks = 0; ks < 4; ks++) {
            float av_[4][4], bv_[4][2];
#pragma unroll
            for (int mi = 0; mi < 4; mi++) {
                const float* p = a_s + mi * 16 * G_LDP + ks * 8 + qc;
                av_[mi][0] = to_tf32(p[0]);
                av_[mi][1] = to_tf32(p[8 * G_LDP]);
                av_[mi][2] = to_tf32(p[4]);
                av_[mi][3] = to_tf32(p[8 * G_LDP + 4]);
            }
#pragma unroll
            for (int ni = 0; ni < 4; ni++) {
                const float* p = b_s + ni * 8 * G_LDP + ks * 8 + qc;
                bv_[ni][0] = to_tf32(p[0]);
                bv_[ni][1] = to_tf32(p[4]);
            }
#pragma unroll
            for (int mi = 0; mi < 4; mi++)
#pragma unroll
                for (int ni = 0; ni < 4; ni++)
                    mma_tf32(acc[mi][ni], av_[mi], bv_[ni]);
        }
        if (it + 2 < nst) {
            const int kt = it + 2;
            const float* as = Ag + kt * 32;
            const float* bs = Bg + kt * 32;
            const uint32_t ad = adst + nxt * G_STG * 4;
            const uint32_t bd = bdst + nxt * G_STG * 4;
#pragma unroll
            for (int j = 0; j < 4; j++) {
                cp16(ad + j * 16, as + j * 4);
                cp16(bd + j * 16, bs + j * 4);
            }
            asm volatile("cp.async.commit_group;" ::: "memory");
        }
        buf = (buf == 2) ? 0 : buf + 1;
        nxt = (nxt == 2) ? 0 : nxt + 1;
    }

#pragma unroll
    for (int mi = 0; mi < 4; mi++) {
        const int r = bym + wr * 64 + mi * 16 + g;
#pragma unroll
        for (int ni = 0; ni < 4; ni++) {
            const int col = bxn + wc * 32 + ni * 8 + qc * 2;
            float2 bv = make_float2(0.f, 0.f);
            if (BIAS) bv = *(const float2*)(bias + col);
            float2 v0, v1;
            v0.x = acc[mi][ni][0] + bv.x;
            v0.y = acc[mi][ni][1] + bv.y;
            v1.x = acc[mi][ni][2] + bv.x;
            v1.y = acc[mi][ni][3] + bv.y;
            if (RELU) {
                v0.x = fmaxf(v0.x, 0.f); v0.y = fmaxf(v0.y, 0.f);
                v1.x = fmaxf(v1.x, 0.f); v1.y = fmaxf(v1.y, 0.f);
            }
            *(float2*)(C + (size_t)r * ldc + col)       = v0;
            *(float2*)(C + (size_t)(r + 8) * ldc + col) = v1;
        }
    }
}

// ====================== flash attention (tf32 mma, online softmax) ===============
// grid: (q-tiles=8, B*H=64). 256 threads = 8 warps, warp w owns 16 q-rows.
#define FL_SQ  0
#define FL_SK  8704           // floats
#define FL_SV  26112
#define FL_MSK 43008
#define FSMEM  ((43008 + 66) * 4)

template<bool CAUSAL>
__global__ void __launch_bounds__(256, 1)
flash_k(const float* __restrict__ Qg, const float* __restrict__ Kg,
        const float* __restrict__ Vg, const unsigned char* __restrict__ padg,
        float* __restrict__ Og, int ldq, int ldk)
{
    extern __shared__ float sm[];
    const int tid = threadIdx.x, lane = tid & 31, w = tid >> 5;
    const int g = lane >> 2, qc = lane & 3;
    const int qt = blockIdx.x;
    const int z = blockIdx.y, b = z >> 4, h = z & 15;

    const float* Qp = Qg + (size_t)b * TT * ldq + h * 64;
    const float* Kp = Kg + (size_t)b * TT * ldk + h * 64;
    const float* Vp = Vg + ((size_t)b * CC + h * 64) * TT;
    const unsigned char* padp = padg + (size_t)b * TT;
    float* Op = Og + (size_t)b * TT * CC + h * 64;

    const uint32_t sQa = smem_u32(sm);
    const uint32_t sKa = sQa + FL_SK * 4;
    const uint32_t sVa = sQa + FL_SV * 4;
    uint32_t* sMskp = (uint32_t*)(sm + FL_MSK);

    const int nkt = CAUSAL ? qt + 1 : (TT / 128);

    {
        const float* qs = Qp + (size_t)(qt * 128 + (tid >> 1)) * ldq + (tid & 1) * 32;
        uint32_t qd = sQa + (tid >> 1) * 272 + (tid & 1) * 128;
#pragma unroll
        for (int j = 0; j < 8; j++) cp16(qd + j * 16, qs + j * 4);
    }
    auto issue_kv = [&](int kt, int buf) {
        const float* ks = Kp + (size_t)(kt * 128 + (tid >> 1)) * ldk + (tid & 1) * 32;
        uint32_t kd = sKa + buf * 34816u + (tid >> 1) * 272 + (tid & 1) * 128;
#pragma unroll
        for (int j = 0; j < 8; j++) cp16(kd + j * 16, ks + j * 4);
        const float* vs = Vp + (size_t)(tid >> 2) * TT + kt * 128 + (tid & 3) * 32;
        uint32_t vd = sVa + buf * 33792u + (tid >> 2) * 528 + (tid & 3) * 128;
#pragma unroll
        for (int j = 0; j < 8; j++) cp16(vd + j * 16, vs + j * 4);
        if (tid < 32) {
            uint32_t mv = *(const uint32_t*)(padp + (size_t)kt * 128 + tid * 4);
            sMskp[buf * 32 + tid] = mv;
            uint32_t f = __reduce_or_sync(0xffffffffu, mv);
            if (tid == 0) sMskp[64 + buf] = f;
        }
    };
    issue_kv(0, 0);
    asm volatile("cp.async.commit_group;" ::: "memory");

    float m0 = -INFINITY, m1 = -INFINITY, l0 = 0.f, l1 = 0.f;
    float oacc[8][4];
#pragma unroll
    for (int j = 0; j < 8; j++)
#pragma unroll
        for (int r = 0; r < 4; r++) oacc[j][r] = 0.f;

    const int r0 = w * 16 + g, r1 = r0 + 8;
    const int s0l = (lane & ~3) | (qc >> 1), s1l = s0l + 2;
    const bool odd = (qc & 1) != 0;

    for (int kt = 0; kt < nkt; ++kt) {
        const int buf = kt & 1;
        if (kt + 1 < nkt) {
            issue_kv(kt + 1, buf ^ 1);
            asm volatile("cp.async.commit_group;" ::: "memory");
            asm volatile("cp.async.wait_group 1;" ::: "memory");
        } else {
            asm volatile("cp.async.wait_group 0;" ::: "memory");
        }
        __syncthreads();

        float aq[8][4];
        {
            const float* qr = sm + (size_t)(w * 16 + g) * 68;
#pragma unroll
            for (int ks = 0; ks < 8; ks++) {
                aq[ks][0] = qr[ks * 8 + qc];
                aq[ks][1] = qr[8 * 68 + ks * 8 + qc];
                aq[ks][2] = qr[ks * 8 + qc + 4];
                aq[ks][3] = qr[8 * 68 + ks * 8 + qc + 4];
            }
        }
        float sacc[16][4];
#pragma unroll
        for (int ni = 0; ni < 16; ni++)
#pragma unroll
            for (int r = 0; r < 4; r++) sacc[ni][r] = 0.f;
        {
            const float* kb = sm + FL_SK + buf * 8704;
#pragma unroll
            for (int ks = 0; ks < 8; ks++)
#pragma unroll
                for (int ni = 0; ni < 16; ni++) {
                    const float* kr = kb + (ni * 8 + g) * 68 + ks * 8;
                    float bv[2] = { kr[qc], kr[qc + 4] };
                    mma_tf32(sacc[ni], aq[ks], bv);
                }
        }

        const uint32_t pf = sMskp[64 + buf];
        const unsigned char* mb = (const unsigned char*)(sMskp + buf * 32);
        float tm0 = -INFINITY, tm1 = -INFINITY;
#pragma unroll
        for (int ni = 0; ni < 16; ni++) {
            float s0 = sacc[ni][0] * 0.125f, s1 = sacc[ni][1] * 0.125f;
            float s2 = sacc[ni][2] * 0.125f, s3 = sacc[ni][3] * 0.125f;
            const int c0 = ni * 8 + qc * 2;
            if (CAUSAL && kt == qt) {
                if (c0     > r0) s0 = -INFINITY;
                if (c0 + 1 > r0) s1 = -INFINITY;
                if (c0     > r1) s2 = -INFINITY;
                if (c0 + 1 > r1) s3 = -INFINITY;
            }
            if (pf) {
                if (mb[c0])     { s0 = -INFINITY; s2 = -INFINITY; }
                if (mb[c0 + 1]) { s1 = -INFINITY; s3 = -INFINITY; }
            }
            sacc[ni][0] = s0; sacc[ni][1] = s1; sacc[ni][2] = s2; sacc[ni][3] = s3;
            tm0 = fmaxf(tm0, fmaxf(s0, s1));
            tm1 = fmaxf(tm1, fmaxf(s2, s3));
        }
        tm0 = fmaxf(tm0, __shfl_xor_sync(0xffffffffu, tm0, 1));
        tm0 = fmaxf(tm0, __shfl_xor_sync(0xffffffffu, tm0, 2));
        tm1 = fmaxf(tm1, __shfl_xor_sync(0xffffffffu, tm1, 1));
        tm1 = fmaxf(tm1, __shfl_xor_sync(0xffffffffu, tm1, 2));
        const float mn0 = fmaxf(m0, tm0), mn1 = fmaxf(m1, tm1);

        float sum0 = 0.f, sum1 = 0.f;
#pragma unroll
        for (int ni = 0; ni < 16; ni++) {
            float p0 = __expf(sacc[ni][0] - mn0);
            float p1 = __expf(sacc[ni][1] - mn0);
            float p2 = __expf(sacc[ni][2] - mn1);
            float p3 = __expf(sacc[ni][3] - mn1);
            sacc[ni][0] = p0; sacc[ni][1] = p1; sacc[ni][2] = p2; sacc[ni][3] = p3;
            sum0 += p0 + p1; sum1 += p2 + p3;
        }
        sum0 += __shfl_xor_sync(0xffffffffu, sum0, 1);
        sum0 += __shfl_xor_sync(0xffffffffu, sum0, 2);
        sum1 += __shfl_xor_sync(0xffffffffu, sum1, 1);
        sum1 += __shfl_xor_sync(0xffffffffu, sum1, 2);

        const float sc0 = __expf(m0 - mn0), sc1 = __expf(m1 - mn1);
        l0 = l0 * sc0 + sum0;  l1 = l1 * sc1 + sum1;
        m0 = mn0;  m1 = mn1;
#pragma unroll
        for (int nj = 0; nj < 8; nj++) {
            oacc[nj][0] *= sc0; oacc[nj][1] *= sc0;
            oacc[nj][2] *= sc1; oacc[nj][3] *= sc1;
        }

        {
            const float* vb = sm + FL_SV + buf * 8448;
#pragma unroll
            for (int k2 = 0; k2 < 16; k2++) {
                float v00 = __shfl_sync(0xffffffffu, sacc[k2][0], s0l);
                float v01 = __shfl_sync(0xffffffffu, sacc[k2][1], s0l);
                float v20 = __shfl_sync(0xffffffffu, sacc[k2][2], s0l);
                float v21 = __shfl_sync(0xffffffffu, sacc[k2][3], s0l);
                float w00 = __shfl_sync(0xffffffffu, sacc[k2][0], s1l);
                float w01 = __shfl_sync(0xffffffffu, sacc[k2][1], s1l);
                float w20 = __shfl_sync(0xffffffffu, sacc[k2][2], s1l);
                float w21 = __shfl_sync(0xffffffffu, sacc[k2][3], s1l);
                float pa[4];
                pa[0] = to_tf32(odd ? v01 : v00);
                pa[1] = to_tf32(odd ? v21 : v20);
                pa[2] = to_tf32(odd ? w01 : w00);
                pa[3] = to_tf32(odd ? w21 : w20);
#pragma unroll
                for (int nj = 0; nj < 8; nj++) {
                    const float* vr = vb + (nj * 8 + g) * 132 + k2 * 8;
                    float bv[2] = { vr[qc], vr[qc + 4] };
                    mma_tf32(oacc[nj], pa, bv);
                }
            }
        }
        __syncthreads();
    }

    const float inv0 = 1.f / l0, inv1 = 1.f / l1;
    float* orow0 = Op + (size_t)(qt * 128 + r0) * CC;
    float* orow1 = orow0 + 8 * CC;
#pragma unroll
    for (int nj = 0; nj < 8; nj++) {
        *(float2*)(orow0 + nj * 8 + qc * 2) =
            make_float2(oacc[nj][0] * inv0, oacc[nj][1] * inv0);
        *(float2*)(orow1 + nj * 8 + qc * 2) =
            make_float2(oacc[nj][2] * inv1, oacc[nj][3] * inv1);
    }
}

// ============================ layernorm ==========================================
__device__ __forceinline__ float warpSum(float v) {
#pragma unroll
    for (int o = 16; o; o >>= 1) v += __shfl_xor_sync(0xffffffffu, v, o);
    return v;
}

__global__ void __launch_bounds__(256)
add_ln(const float* __restrict__ X, const float* __restrict__ R,
       const float* __restrict__ g, const float* __restrict__ be,
       float* __restrict__ out)
{
    const size_t row = blockIdx.x;
    const int tid = threadIdx.x;
    const int col = tid * 4;
    float4 xv = *(const float4*)(X + row * CC + col);
    float4 rv = *(const float4*)(R + row * CC + col);
    float4 v;
    v.x = xv.x + rv.x; v.y = xv.y + rv.y; v.z = xv.z + rv.z; v.w = xv.w + rv.w;

    __shared__ float sh1[8], sh2[8];
    float s = (v.x + v.y) + (v.z + v.w);
    float sq = v.x * v.x + v.y * v.y + v.z * v.z + v.w * v.w;
    s = warpSum(s); sq = warpSum(sq);
    if ((tid & 31) == 0) { sh1[tid >> 5] = s; sh2[tid >> 5] = sq; }
    __syncthreads();
    s  = (sh1[0] + sh1[1]) + (sh1[2] + sh1[3]) + (sh1[4] + sh1[5]) + (sh1[6] + sh1[7]);
    sq = (sh2[0] + sh2[1]) + (sh2[2] + sh2[3]) + (sh2[4] + sh2[5]) + (sh2[6] + sh2[7]);
    const float mean = s * (1.0f / CC);
    const float var = sq * (1.0f / CC) - mean * mean;
    const float rstd = rsqrtf(var + 1e-5f);

    float4 gg = *(const float4*)(g + col);
    float4 bb = *(const float4*)(be + col);
    float4 o;
    o.x = (v.x - mean) * rstd * gg.x + bb.x;
    o.y = (v.y - mean) * rstd * gg.y + bb.y;
    o.z = (v.z - mean) * rstd * gg.z + bb.z;
    o.w = (v.w - mean) * rstd * gg.w + bb.w;
    *(float4*)(out + row * CC + col) = o;
}

// ------------------------------- launcher ---------------------------------------
extern "C" void kernel_launch(void* const* d_in, const int* in_sizes, int n_in,
                              void* d_out, int out_size)
{
    const float* x    = (const float*)d_in[0];
    const float* enc  = (const float*)d_in[1];
    const unsigned char* tmask = (const unsigned char*)d_in[2];
    const unsigned char* smask = (const unsigned char*)d_in[3];
    const float* Wq1 = (const float*)d_in[4];
    const float* Wk1 = (const float*)d_in[5];
    const float* Wv1 = (const float*)d_in[6];
    const float* Wo1 = (const float*)d_in[7];
    const float* ln1g = (const float*)d_in[8];
    const float* ln1b = (const float*)d_in[9];
    const float* Wq2 = (const float*)d_in[10];
    const float* Wk2 = (const float*)d_in[11];
    const float* Wv2 = (const float*)d_in[12];
    const float* Wo2 = (const float*)d_in[13];
    const float* ln2g = (const float*)d_in[14];
    const float* ln2b = (const float*)d_in[15];
    const float* Wf1 = (const float*)d_in[16];
    const float* bf1 = (const float*)d_in[17];
    const float* Wf2 = (const float*)d_in[18];
    const float* bf2 = (const float*)d_in[19];
    const float* ln3g = (const float*)d_in[20];
    const float* ln3b = (const float*)d_in[21];
    float* out = (float*)d_out;

    float *gq, *gvt, *gctx, *go, *gx1, *gx2, *gff, *gwt;
    cudaGetSymbolAddress((void**)&gq,  g_q);
    cudaGetSymbolAddress((void**)&gvt, g_vt);
    cudaGetSymbolAddress((void**)&gctx, g_ctx);
    cudaGetSymbolAddress((void**)&go,  g_o);
    cudaGetSymbolAddress((void**)&gx1, g_x1);
    cudaGetSymbolAddress((void**)&gx2, g_x2);
    cudaGetSymbolAddress((void**)&gff, g_ff);
    cudaGetSymbolAddress((void**)&gwt, g_wt);

    float* tq1 = gwt + 0u * 1048576u;    // tq1,tk1,tv1 contiguous -> [3072,1024]
    float* tk1 = gwt + 1u * 1048576u;
    float* tv1 = gwt + 2u * 1048576u;
    float* to1 = gwt + 3u * 1048576u;
    float* tq2 = gwt + 4u * 1048576u;
    float* tk2 = gwt + 5u * 1048576u;    // tk2,tv2 contiguous -> [2048,1024]
    float* tv2 = gwt + 6u * 1048576u;
    float* to2 = gwt + 7u * 1048576u;
    float* tf1 = gwt + 8u * 1048576u;               // [F, C]
    float* tf2 = gwt + 8u * 1048576u + 4194304u;    // [C, F]

    auto* kProj  = gemm_mma<false, false>;
    auto* kFfn1  = gemm_mma<true,  true >;
    auto* kFfn2  = gemm_mma<true,  false>;
    cudaFuncSetAttribute(kProj, cudaFuncAttributeMaxDynamicSharedMemorySize, GSMEM);
    cudaFuncSetAttribute(kFfn1, cudaFuncAttributeMaxDynamicSharedMemorySize, GSMEM);
    cudaFuncSetAttribute(kFfn2, cudaFuncAttributeMaxDynamicSharedMemorySize, GSMEM);
    cudaFuncSetAttribute(flash_k<true>,  cudaFuncAttributeMaxDynamicSharedMemorySize, FSMEM);
    cudaFuncSetAttribute(flash_k<false>, cudaFuncAttributeMaxDynamicSharedMemorySize, FSMEM);

    const dim3 blk(256);
    const dim3 tblk(32, 8);

    // ---- weight transposes (K-major B operands) ----
    transpose_k<<<dim3(CC/32, CC/32), tblk>>>(Wq1, tq1, CC, CC);
    transpose_k<<<dim3(CC/32, CC/32), tblk>>>(Wk1, tk1, CC, CC);
    transpose_k<<<dim3(CC/32, CC/32), tblk>>>(Wv1, tv1, CC, CC);
    transpose_k<<<dim3(CC/32, CC/32), tblk>>>(Wo1, to1, CC, CC);
    transpose_k<<<dim3(CC/32, CC/32), tblk>>>(Wq2, tq2, CC, CC);
    transpose_k<<<dim3(CC/32, CC/32), tblk>>>(Wk2, tk2, CC, CC);
    transpose_k<<<dim3(CC/32, CC/32), tblk>>>(Wv2, tv2, CC, CC);
    transpose_k<<<dim3(CC/32, CC/32), tblk>>>(Wo2, to2, CC, CC);
    transpose_k<<<dim3(FF/32, CC/32), tblk>>>(Wf1, tf1, CC, FF);
    transpose_k<<<dim3(CC/32, FF/32), tblk>>>(Wf2, tf2, FF, CC);

    const dim3 gQKV(3072/128, MM/128);   // (24, 32) fused self QKV
    const dim3 gKV (2048/128, MM/128);   // (16, 32) fused cross KV
    const dim3 gP  (CC/128,   MM/128);   // (8, 32)
    const dim3 gF1 (FF/128,   MM/128);   // (32, 32)
    const dim3 gFl (TT/128, BB*HH);      // (8, 64)
    const dim3 gVt (CC/32, TT/32, BB);
    const int nLn = MM;

    // ---- self-attention (causal) ----
    kProj<<<gQKV, blk, GSMEM>>>(x, tq1, nullptr, gff, CC, CC, CC, 3072);
    transpose_v<<<gVt, tblk>>>(gff + 2048, gvt, 3072);
    flash_k<true><<<gFl, blk, FSMEM>>>(gff, gff + 1024, gvt, tmask, gctx, 3072, 3072);
    kProj<<<gP, blk, GSMEM>>>(gctx, to1, nullptr, go, CC, CC, CC, CC);
    add_ln<<<nLn, blk>>>(x, go, ln1g, ln1b, gx1);

    // ---- cross-attention ----
    kProj<<<gP,  blk, GSMEM>>>(gx1, tq2, nullptr, gq, CC, CC, CC, CC);
    kProj<<<gKV, blk, GSMEM>>>(enc, tk2, nullptr, gff, CC, CC, CC, 2048);
    transpose_v<<<gVt, tblk>>>(gff + 1024, gvt, 2048);
    flash_k<false><<<gFl, blk, FSMEM>>>(gq, gff, gvt, smask, gctx, CC, 2048);
    kProj<<<gP, blk, GSMEM>>>(gctx, to2, nullptr, go, CC, CC, CC, CC);
    add_ln<<<nLn, blk>>>(gx1, go, ln2g, ln2b, gx2);

    // ---- FFN ----
    kFfn1<<<gF1, blk, GSMEM>>>(gx2, tf1, bf1, gff, CC, CC, CC, FF);
    kFfn2<<<gP,  blk, GSMEM>>>(gff, tf2, bf2, go, FF, FF, FF, CC);
    add_ln<<<nLn, blk>>>(gx2, go, ln3g, ln3b, out);
}

// round 6
// speedup vs baseline: 2.7243x; 1.0246x over previous
#include <cuda_runtime.h>
#include <cstdint>
#include <cstddef>

// Problem constants
#define BB 4
#define TT 1024
#define CC 1024
#define HH 16
#define DH 64
#define FF 4096
#define MM (BB*TT)          // 4096 rows

// ---------------- scratch (device globals; no allocation allowed) ----------------
__device__ float g_q  [(size_t)MM*CC];
__device__ float g_vt [(size_t)MM*CC];         // V transposed per batch: [B][C][T]
__device__ float g_ctx[(size_t)MM*CC];
__device__ float g_o  [(size_t)MM*CC];
__device__ float g_x1 [(size_t)MM*CC];
__device__ float g_x2 [(size_t)MM*CC];
__device__ float g_ff [(size_t)MM*FF];         // 64 MB (also holds fused QKV / KV)
__device__ float g_xr [(size_t)MM*CC];         // tf32-rounded x
__device__ float g_er [(size_t)MM*CC];         // tf32-rounded enc
// transposed weights: 8 x [1024x1024] + Wf1^T [4096x1024] + Wf2^T [1024x4096]
__device__ float g_wt [8u*1024u*1024u + 2u*4096u*1024u];

// ============================ small helpers ======================================
__device__ __forceinline__ float to_tf32(float x) {
    uint32_t o;
    asm("cvt.rna.tf32.f32 %0, %1;" : "=r"(o) : "r"(__float_as_uint(x)));
    return __uint_as_float(o);
}
__device__ __forceinline__ void mma_tf32(float* d, const float* a, const float* b) {
    asm volatile(
        "mma.sync.aligned.m16n8k8.row.col.f32.tf32.tf32.f32 "
        "{%0,%1,%2,%3},{%4,%5,%6,%7},{%8,%9},{%0,%1,%2,%3};"
        : "+f"(d[0]), "+f"(d[1]), "+f"(d[2]), "+f"(d[3])
        : "r"(__float_as_uint(a[0])), "r"(__float_as_uint(a[1])),
          "r"(__float_as_uint(a[2])), "r"(__float_as_uint(a[3])),
          "r"(__float_as_uint(b[0])), "r"(__float_as_uint(b[1])));
}
__device__ __forceinline__ uint32_t smem_u32(const void* p) {
    uint32_t a;
    asm("{ .reg .u64 t; cvta.to.shared.u64 t, %1; cvt.u32.u64 %0, t; }" : "=r"(a) : "l"(p));
    return a;
}
__device__ __forceinline__ void cp16(uint32_t dst, const void* src) {
    asm volatile("cp.async.cg.shared.global [%0], [%1], 16;" :: "r"(dst), "l"(src));
}

// =================== tf32 rounding copy (producer-side rounding) =================
__global__ void __launch_bounds__(256)
round_copy(const float* __restrict__ in, float* __restrict__ out)
{
    const size_t i = ((size_t)blockIdx.x * 256 + threadIdx.x) * 4;
    float4 v = *(const float4*)(in + i);
    v.x = to_tf32(v.x); v.y = to_tf32(v.y); v.z = to_tf32(v.z); v.w = to_tf32(v.w);
    *(float4*)(out + i) = v;
}

// ====================== 32x32 tiled transposes (tf32-rounding) ===================
struct Ptr8 { const float* s[8]; float* d[8]; };

__global__ void __launch_bounds__(256)
transpose8(Ptr8 ps)   // 8 square [CC x CC] weights, z selects matrix
{
    const float* in = ps.s[blockIdx.z];
    float* out = ps.d[blockIdx.z];
    __shared__ float t[32][33];
    const int bx = blockIdx.x * 32, by = blockIdx.y * 32;
    int x = bx + threadIdx.x;
#pragma unroll
    for (int i = 0; i < 32; i += 8)
        t[threadIdx.y + i][threadIdx.x] = in[(size_t)(by + threadIdx.y + i) * CC + x];
    __syncthreads();
    x = by + threadIdx.x;
#pragma unroll
    for (int i = 0; i < 32; i += 8)
        out[(size_t)(bx + threadIdx.y + i) * CC + x] = to_tf32(t[threadIdx.x][threadIdx.y + i]);
}

__global__ void __launch_bounds__(256)
transpose_k(const float* __restrict__ in, float* __restrict__ out, int R, int C)
{
    __shared__ float t[32][33];
    const int bx = blockIdx.x * 32, by = blockIdx.y * 32;
    int x = bx + threadIdx.x;
#pragma unroll
    for (int i = 0; i < 32; i += 8)
        t[threadIdx.y + i][threadIdx.x] = in[(size_t)(by + threadIdx.y + i) * C + x];
    __syncthreads();
    x = by + threadIdx.x;
#pragma unroll
    for (int i = 0; i < 32; i += 8)
        out[(size_t)(bx + threadIdx.y + i) * R + x] = to_tf32(t[threadIdx.x][threadIdx.y + i]);
}

// extract + transpose V block out of a packed [B*T, ldin] buffer -> [B][C][T]
__global__ void __launch_bounds__(256)
transpose_v(const float* __restrict__ in, float* __restrict__ out, int ldin)
{
    in  += (size_t)blockIdx.z * TT * ldin;
    out += (size_t)blockIdx.z * CC * TT;
    __shared__ float t[32][33];
    const int bx = blockIdx.x * 32, by = blockIdx.y * 32;   // bx: C dim, by: T dim
#pragma unroll
    for (int i = 0; i < 32; i += 8)
        t[threadIdx.y + i][threadIdx.x] =
            in[(size_t)(by + threadIdx.y + i) * ldin + bx + threadIdx.x];
    __syncthreads();
#pragma unroll
    for (int i = 0; i < 32; i += 8)
        out[(size_t)(bx + threadIdx.y + i) * TT + by + threadIdx.x] =
            to_tf32(t[threadIdx.x][threadIdx.y + i]);
}

// ================= tf32 mma.sync GEMM: C[M,N] = A[M,K] @ Bt[N,K]^T ===============
// Inputs assumed pre-rounded to tf32 (RNA). No fragment-side cvt.
// cp.async 3-stage pipeline, 128x128 tile, 8 warps (2x4), 2 CTAs/SM.
#define G_LDP 36
#define G_STG (256 * G_LDP)                 // floats per stage (A128 + B128 rows)
#define GSMEM (3 * G_STG * 4)               // 110592 bytes

template<bool BIAS, bool RELU, bool ROUND>
__global__ void __launch_bounds__(256, 2)
gemm_mma(const float* __restrict__ A, const float* __restrict__ Bt,
         const float* __restrict__ bias, float* __restrict__ C,
         int K, int lda, int ldb, int ldc)
{
    extern __shared__ float smf[];
    const int bxn = blockIdx.x * 128, bym = blockIdx.y * 128;
    const int tid = threadIdx.x, wid = tid >> 5, lane = tid & 31;
    const int wr = wid >> 2, wc = wid & 3;      // 2 x 4 warps
    const int g = lane >> 2, qc = lane & 3;

    const int row = tid >> 1, colb = (tid & 1) * 16;
    const float* Ag = A  + (size_t)(bym + row) * lda + colb;
    const float* Bg = Bt + (size_t)(bxn + row) * ldb + colb;
    const uint32_t adst = smem_u32(smf) + (uint32_t)(row * G_LDP + colb) * 4;
    const uint32_t bdst = adst + 128 * G_LDP * 4;

    float acc[4][4][4];
#pragma unroll
    for (int i = 0; i < 4; i++)
#pragma unroll
        for (int j = 0; j < 4; j++)
#pragma unroll
            for (int r = 0; r < 4; r++) acc[i][j][r] = 0.f;

    const int nst = K >> 5;

#pragma unroll
    for (int s = 0; s < 2; s++) {
        const float* as = Ag + s * 32;
        const float* bs = Bg + s * 32;
        const uint32_t ad = adst + s * G_STG * 4;
        const uint32_t bd = bdst + s * G_STG * 4;
#pragma unroll
        for (int j = 0; j < 4; j++) {
            cp16(ad + j * 16, as + j * 4);
            cp16(bd + j * 16, bs + j * 4);
        }
        asm volatile("cp.async.commit_group;" ::: "memory");
    }

    int buf = 0, nxt = 2;
    for (int it = 0; it < nst; ++it) {
        asm volatile("cp.async.wait_group 1;" ::: "memory");
        __syncthreads();
        const float* a_s = smf + buf * G_STG + (wr * 64 + g) * G_LDP;
        const float* b_s = smf + buf * G_STG + 128 * G_LDP + (wc * 32 + g) * G_LDP;
#pragma unroll
        for (int ks = 0; ks < 4; ks++) {
            float av_[4][4], bv_[4][2];
#pragma unroll
            for (int mi = 0; mi < 4; mi++) {
                const float* p = a_s + mi * 16 * G_LDP + ks * 8 + qc;
                av_[mi][0] = p[0];
                av_[mi][1] = p[8 * G_LDP];
                av_[mi][2] = p[4];
                av_[mi][3] = p[8 * G_LDP + 4];
            }
#pragma unroll
            for (int ni = 0; ni < 4; ni++) {
                const float* p = b_s + ni * 8 * G_LDP + ks * 8 + qc;
                bv_[ni][0] = p[0];
                bv_[ni][1] = p[4];
            }
#pragma unroll
            for (int mi = 0; mi < 4; mi++)
#pragma unroll
                for (int ni = 0; ni < 4; ni++)
                    mma_tf32(acc[mi][ni], av_[mi], bv_[ni]);
        }
        if (it + 2 < nst) {
            const int kt = it + 2;
            const float* as = Ag + kt * 32;
            const float* bs = Bg + kt * 32;
            const uint32_t ad = adst + nxt * G_STG * 4;
            const uint32_t bd = bdst + nxt * G_STG * 4;
#pragma unroll
            for (int j = 0; j < 4; j++) {
                cp16(ad + j * 16, as + j * 4);
                cp16(bd + j * 16, bs + j * 4);
            }
            asm volatile("cp.async.commit_group;" ::: "memory");
        }
        buf = (buf == 2) ? 0 : buf + 1;
        nxt = (nxt == 2) ? 0 : nxt + 1;
    }

#pragma unroll
    for (int mi = 0; mi < 4; mi++) {
        const int r = bym + wr * 64 + mi * 16 + g;
#pragma unroll
        for (int ni = 0; ni < 4; ni++) {
            const int col = bxn + wc * 32 + ni * 8 + qc * 2;
            float2 bv = make_float2(0.f, 0.f);
            if (BIAS) bv = *(const float2*)(bias + col);
            float2 v0, v1;
            v0.x = acc[mi][ni][0] + bv.x;
            v0.y = acc[mi][ni][1] + bv.y;
            v1.x = acc[mi][ni][2] + bv.x;
            v1.y = acc[mi][ni][3] + bv.y;
            if (RELU) {
                v0.x = fmaxf(v0.x, 0.f); v0.y = fmaxf(v0.y, 0.f);
                v1.x = fmaxf(v1.x, 0.f); v1.y = fmaxf(v1.y, 0.f);
            }
            if (ROUND) {
                v0.x = to_tf32(v0.x); v0.y = to_tf32(v0.y);
                v1.x = to_tf32(v1.x); v1.y = to_tf32(v1.y);
            }
            *(float2*)(C + (size_t)r * ldc + col)       = v0;
            *(float2*)(C + (size_t)(r + 8) * ldc + col) = v1;
        }
    }
}

// ====================== flash attention (tf32 mma, online softmax) ===============
#define FL_SQ  0
#define FL_SK  8704           // floats
#define FL_SV  26112
#define FL_MSK 43008
#define FSMEM  ((43008 + 66) * 4)

template<bool CAUSAL>
__global__ void __launch_bounds__(256, 1)
flash_k(const float* __restrict__ Qg, const float* __restrict__ Kg,
        const float* __restrict__ Vg, const unsigned char* __restrict__ padg,
        float* __restrict__ Og, int ldq, int ldk)
{
    extern __shared__ float sm[];
    const int tid = threadIdx.x, lane = tid & 31, w = tid >> 5;
    const int g = lane >> 2, qc = lane & 3;
    const int qt = blockIdx.x;
    const int z = blockIdx.y, b = z >> 4, h = z & 15;

    const float* Qp = Qg + (size_t)b * TT * ldq + h * 64;
    const float* Kp = Kg + (size_t)b * TT * ldk + h * 64;
    const float* Vp = Vg + ((size_t)b * CC + h * 64) * TT;
    const unsigned char* padp = padg + (size_t)b * TT;
    float* Op = Og + (size_t)b * TT * CC + h * 64;

    const uint32_t sQa = smem_u32(sm);
    const uint32_t sKa = sQa + FL_SK * 4;
    const uint32_t sVa = sQa + FL_SV * 4;
    uint32_t* sMskp = (uint32_t*)(sm + FL_MSK);

    const int nkt = CAUSAL ? qt + 1 : (TT / 128);

    {
        const float* qs = Qp + (size_t)(qt * 128 + (tid >> 1)) * ldq + (tid & 1) * 32;
        uint32_t qd = sQa + (tid >> 1) * 272 + (tid & 1) * 128;
#pragma unroll
        for (int j = 0; j < 8; j++) cp16(qd + j * 16, qs + j * 4);
    }
    auto issue_kv = [&](int kt, int buf) {
        const float* ks = Kp + (size_t)(kt * 128 + (tid >> 1)) * ldk + (tid & 1) * 32;
        uint32_t kd = sKa + buf * 34816u + (tid >> 1) * 272 + (tid & 1) * 128;
#pragma unroll
        for (int j = 0; j < 8; j++) cp16(kd + j * 16, ks + j * 4);
        const float* vs = Vp + (size_t)(tid >> 2) * TT + kt * 128 + (tid & 3) * 32;
        uint32_t vd = sVa + buf * 33792u + (tid >> 2) * 528 + (tid & 3) * 128;
#pragma unroll
        for (int j = 0; j < 8; j++) cp16(vd + j * 16, vs + j * 4);
        if (tid < 32) {
            uint32_t mv = *(const uint32_t*)(padp + (size_t)kt * 128 + tid * 4);
            sMskp[buf * 32 + tid] = mv;
            uint32_t f = __reduce_or_sync(0xffffffffu, mv);
            if (tid == 0) sMskp[64 + buf] = f;
        }
    };
    issue_kv(0, 0);
    asm volatile("cp.async.commit_group;" ::: "memory");

    float m0 = -INFINITY, m1 = -INFINITY, l0 = 0.f, l1 = 0.f;
    float oacc[8][4];
#pragma unroll
    for (int j = 0; j < 8; j++)
#pragma unroll
        for (int r = 0; r < 4; r++) oacc[j][r] = 0.f;

    const int r0 = w * 16 + g, r1 = r0 + 8;
    const int s0l = (lane & ~3) | (qc >> 1), s1l = s0l + 2;
    const bool odd = (qc & 1) != 0;

    for (int kt = 0; kt < nkt; ++kt) {
        const int buf = kt & 1;
        if (kt + 1 < nkt) {
            issue_kv(kt + 1, buf ^ 1);
            asm volatile("cp.async.commit_group;" ::: "memory");
            asm volatile("cp.async.wait_group 1;" ::: "memory");
        } else {
            asm volatile("cp.async.wait_group 0;" ::: "memory");
        }
        __syncthreads();

        float aq[8][4];
        {
            const float* qr = sm + (size_t)(w * 16 + g) * 68;
#pragma unroll
            for (int ks = 0; ks < 8; ks++) {
                aq[ks][0] = qr[ks * 8 + qc];
                aq[ks][1] = qr[8 * 68 + ks * 8 + qc];
                aq[ks][2] = qr[ks * 8 + qc + 4];
                aq[ks][3] = qr[8 * 68 + ks * 8 + qc + 4];
            }
        }
        float sacc[16][4];
#pragma unroll
        for (int ni = 0; ni < 16; ni++)
#pragma unroll
            for (int r = 0; r < 4; r++) sacc[ni][r] = 0.f;
        {
            const float* kb = sm + FL_SK + buf * 8704;
#pragma unroll
            for (int ks = 0; ks < 8; ks++)
#pragma unroll
                for (int ni = 0; ni < 16; ni++) {
                    const float* kr = kb + (ni * 8 + g) * 68 + ks * 8;
                    float bv[2] = { kr[qc], kr[qc + 4] };
                    mma_tf32(sacc[ni], aq[ks], bv);
                }
        }

        const uint32_t pf = sMskp[64 + buf];
        const unsigned char* mb = (const unsigned char*)(sMskp + buf * 32);
        float tm0 = -INFINITY, tm1 = -INFINITY;
#pragma unroll
        for (int ni = 0; ni < 16; ni++) {
            float s0 = sacc[ni][0] * 0.125f, s1 = sacc[ni][1] * 0.125f;
            float s2 = sacc[ni][2] * 0.125f, s3 = sacc[ni][3] * 0.125f;
            const int c0 = ni * 8 + qc * 2;
            if (CAUSAL && kt == qt) {
                if (c0     > r0) s0 = -INFINITY;
                if (c0 + 1 > r0) s1 = -INFINITY;
                if (c0     > r1) s2 = -INFINITY;
                if (c0 + 1 > r1) s3 = -INFINITY;
            }
            if (pf) {
                if (mb[c0])     { s0 = -INFINITY; s2 = -INFINITY; }
                if (mb[c0 + 1]) { s1 = -INFINITY; s3 = -INFINITY; }
            }
            sacc[ni][0] = s0; sacc[ni][1] = s1; sacc[ni][2] = s2; sacc[ni][3] = s3;
            tm0 = fmaxf(tm0, fmaxf(s0, s1));
            tm1 = fmaxf(tm1, fmaxf(s2, s3));
        }
        tm0 = fmaxf(tm0, __shfl_xor_sync(0xffffffffu, tm0, 1));
        tm0 = fmaxf(tm0, __shfl_xor_sync(0xffffffffu, tm0, 2));
        tm1 = fmaxf(tm1, __shfl_xor_sync(0xffffffffu, tm1, 1));
        tm1 = fmaxf(tm1, __shfl_xor_sync(0xffffffffu, tm1, 2));
        const float mn0 = fmaxf(m0, tm0), mn1 = fmaxf(m1, tm1);

        float sum0 = 0.f, sum1 = 0.f;
#pragma unroll
        for (int ni = 0; ni < 16; ni++) {
            float p0 = __expf(sacc[ni][0] - mn0);
            float p1 = __expf(sacc[ni][1] - mn0);
            float p2 = __expf(sacc[ni][2] - mn1);
            float p3 = __expf(sacc[ni][3] - mn1);
            sacc[ni][0] = p0; sacc[ni][1] = p1; sacc[ni][2] = p2; sacc[ni][3] = p3;
            sum0 += p0 + p1; sum1 += p2 + p3;
        }
        sum0 += __shfl_xor_sync(0xffffffffu, sum0, 1);
        sum0 += __shfl_xor_sync(0xffffffffu, sum0, 2);
        sum1 += __shfl_xor_sync(0xffffffffu, sum1, 1);
        sum1 += __shfl_xor_sync(0xffffffffu, sum1, 2);

        const float sc0 = __expf(m0 - mn0), sc1 = __expf(m1 - mn1);
        l0 = l0 * sc0 + sum0;  l1 = l1 * sc1 + sum1;
        m0 = mn0;  m1 = mn1;
#pragma unroll
        for (int nj = 0; nj < 8; nj++) {
            oacc[nj][0] *= sc0; oacc[nj][1] *= sc0;
            oacc[nj][2] *= sc1; oacc[nj][3] *= sc1;
        }

        {
            const float* vb = sm + FL_SV + buf * 8448;
#pragma unroll
            for (int k2 = 0; k2 < 16; k2++) {
                float v00 = __shfl_sync(0xffffffffu, sacc[k2][0], s0l);
                float v01 = __shfl_sync(0xffffffffu, sacc[k2][1], s0l);
                float v20 = __shfl_sync(0xffffffffu, sacc[k2][2], s0l);
                float v21 = __shfl_sync(0xffffffffu, sacc[k2][3], s0l);
                float w00 = __shfl_sync(0xffffffffu, sacc[k2][0], s1l);
                float w01 = __shfl_sync(0xffffffffu, sacc[k2][1], s1l);
                float w20 = __shfl_sync(0xffffffffu, sacc[k2][2], s1l);
                float w21 = __shfl_sync(0xffffffffu, sacc[k2][3], s1l);
                float pa[4];
                pa[0] = to_tf32(odd ? v01 : v00);
                pa[1] = to_tf32(odd ? v21 : v20);
                pa[2] = to_tf32(odd ? w01 : w00);
                pa[3] = to_tf32(odd ? w21 : w20);
#pragma unroll
                for (int nj = 0; nj < 8; nj++) {
                    const float* vr = vb + (nj * 8 + g) * 132 + k2 * 8;
                    float bv[2] = { vr[qc], vr[qc + 4] };
                    mma_tf32(oacc[nj], pa, bv);
                }
            }
        }
        __syncthreads();
    }

    // output rounded to tf32 (consumed as GEMM A operand)
    const float inv0 = 1.f / l0, inv1 = 1.f / l1;
    float* orow0 = Op + (size_t)(qt * 128 + r0) * CC;
    float* orow1 = orow0 + 8 * CC;
#pragma unroll
    for (int nj = 0; nj < 8; nj++) {
        *(float2*)(orow0 + nj * 8 + qc * 2) =
            make_float2(to_tf32(oacc[nj][0] * inv0), to_tf32(oacc[nj][1] * inv0));
        *(float2*)(orow1 + nj * 8 + qc * 2) =
            make_float2(to_tf32(oacc[nj][2] * inv1), to_tf32(oacc[nj][3] * inv1));
    }
}

// ============================ layernorm ==========================================
__device__ __forceinline__ float warpSum(float v) {
#pragma unroll
    for (int o = 16; o; o >>= 1) v += __shfl_xor_sync(0xffffffffu, v, o);
    return v;
}

template<bool ROUND>
__global__ void __launch_bounds__(256)
add_ln(const float* __restrict__ X, const float* __restrict__ R,
       const float* __restrict__ g, const float* __restrict__ be,
       float* __restrict__ out)
{
    const size_t row = blockIdx.x;
    const int tid = threadIdx.x;
    const int col = tid * 4;
    float4 xv = *(const float4*)(X + row * CC + col);
    float4 rv = *(const float4*)(R + row * CC + col);
    float4 v;
    v.x = xv.x + rv.x; v.y = xv.y + rv.y; v.z = xv.z + rv.z; v.w = xv.w + rv.w;

    __shared__ float sh1[8], sh2[8];
    float s = (v.x + v.y) + (v.z + v.w);
    float sq = v.x * v.x + v.y * v.y + v.z * v.z + v.w * v.w;
    s = warpSum(s); sq = warpSum(sq);
    if ((tid & 31) == 0) { sh1[tid >> 5] = s; sh2[tid >> 5] = sq; }
    __syncthreads();
    s  = (sh1[0] + sh1[1]) + (sh1[2] + sh1[3]) + (sh1[4] + sh1[5]) + (sh1[6] + sh1[7]);
    sq = (sh2[0] + sh2[1]) + (sh2[2] + sh2[3]) + (sh2[4] + sh2[5]) + (sh2[6] + sh2[7]);
    const float mean = s * (1.0f / CC);
    const float var = sq * (1.0f / CC) - mean * mean;
    const float rstd = rsqrtf(var + 1e-5f);

    float4 gg = *(const float4*)(g + col);
    float4 bb = *(const float4*)(be + col);
    float4 o;
    o.x = (v.x - mean) * rstd * gg.x + bb.x;
    o.y = (v.y - mean) * rstd * gg.y + bb.y;
    o.z = (v.z - mean) * rstd * gg.z + bb.z;
    o.w = (v.w - mean) * rstd * gg.w + bb.w;
    if (ROUND) {
        o.x = to_tf32(o.x); o.y = to_tf32(o.y);
        o.z = to_tf32(o.z); o.w = to_tf32(o.w);
    }
    *(float4*)(out + row * CC + col) = o;
}

// ------------------------------- launcher ---------------------------------------
extern "C" void kernel_launch(void* const* d_in, const int* in_sizes, int n_in,
                              void* d_out, int out_size)
{
    const float* x    = (const float*)d_in[0];
    const float* enc  = (const float*)d_in[1];
    const unsigned char* tmask = (const unsigned char*)d_in[2];
    const unsigned char* smask = (const unsigned char*)d_in[3];
    const float* Wq1 = (const float*)d_in[4];
    const float* Wk1 = (const float*)d_in[5];
    const float* Wv1 = (const float*)d_in[6];
    const float* Wo1 = (const float*)d_in[7];
    const float* ln1g = (const float*)d_in[8];
    const float* ln1b = (const float*)d_in[9];
    const float* Wq2 = (const float*)d_in[10];
    const float* Wk2 = (const float*)d_in[11];
    const float* Wv2 = (const float*)d_in[12];
    const float* Wo2 = (const float*)d_in[13];
    const float* ln2g = (const float*)d_in[14];
    const float* ln2b = (const float*)d_in[15];
    const float* Wf1 = (const float*)d_in[16];
    const float* bf1 = (const float*)d_in[17];
    const float* Wf2 = (const float*)d_in[18];
    const float* bf2 = (const float*)d_in[19];
    const float* ln3g = (const float*)d_in[20];
    const float* ln3b = (const float*)d_in[21];
    float* out = (float*)d_out;

    float *gq, *gvt, *gctx, *go, *gx1, *gx2, *gff, *gxr, *ger, *gwt;
    cudaGetSymbolAddress((void**)&gq,  g_q);
    cudaGetSymbolAddress((void**)&gvt, g_vt);
    cudaGetSymbolAddress((void**)&gctx, g_ctx);
    cudaGetSymbolAddress((void**)&go,  g_o);
    cudaGetSymbolAddress((void**)&gx1, g_x1);
    cudaGetSymbolAddress((void**)&gx2, g_x2);
    cudaGetSymbolAddress((void**)&gff, g_ff);
    cudaGetSymbolAddress((void**)&gxr, g_xr);
    cudaGetSymbolAddress((void**)&ger, g_er);
    cudaGetSymbolAddress((void**)&gwt, g_wt);

    float* tq1 = gwt + 0u * 1048576u;    // tq1,tk1,tv1 contiguous -> [3072,1024]
    float* tk1 = gwt + 1u * 1048576u;
    float* tv1 = gwt + 2u * 1048576u;
    float* to1 = gwt + 3u * 1048576u;
    float* tq2 = gwt + 4u * 1048576u;
    float* tk2 = gwt + 5u * 1048576u;    // tk2,tv2 contiguous -> [2048,1024]
    float* tv2 = gwt + 6u * 1048576u;
    float* to2 = gwt + 7u * 1048576u;
    float* tf1 = gwt + 8u * 1048576u;               // [F, C]
    float* tf2 = gwt + 8u * 1048576u + 4194304u;    // [C, F]

    auto* kProj  = gemm_mma<false, false, false>;   // plain (out -> add_ln / flash)
    auto* kProjR = gemm_mma<false, false, true >;   // rounded out (out -> GEMM A)
    auto* kFfn1  = gemm_mma<true,  true,  true >;   // bias+relu+rounded (-> FFN2 A)
    auto* kFfn2  = gemm_mma<true,  false, false>;
    cudaFuncSetAttribute(kProj,  cudaFuncAttributeMaxDynamicSharedMemorySize, GSMEM);
    cudaFuncSetAttribute(kProjR, cudaFuncAttributeMaxDynamicSharedMemorySize, GSMEM);
    cudaFuncSetAttribute(kFfn1,  cudaFuncAttributeMaxDynamicSharedMemorySize, GSMEM);
    cudaFuncSetAttribute(kFfn2,  cudaFuncAttributeMaxDynamicSharedMemorySize, GSMEM);
    cudaFuncSetAttribute(flash_k<true>,  cudaFuncAttributeMaxDynamicSharedMemorySize, FSMEM);
    cudaFuncSetAttribute(flash_k<false>, cudaFuncAttributeMaxDynamicSharedMemorySize, FSMEM);

    const dim3 blk(256);
    const dim3 tblk(32, 8);

    // ---- producer-side tf32 rounding of external GEMM A inputs ----
    round_copy<<<MM * CC / 1024, blk>>>(x,   gxr);
    round_copy<<<MM * CC / 1024, blk>>>(enc, ger);

    // ---- weight transposes (K-major, tf32-rounded B operands) ----
    Ptr8 p8;
    p8.s[0] = Wq1; p8.d[0] = tq1;  p8.s[1] = Wk1; p8.d[1] = tk1;
    p8.s[2] = Wv1; p8.d[2] = tv1;  p8.s[3] = Wo1; p8.d[3] = to1;
    p8.s[4] = Wq2; p8.d[4] = tq2;  p8.s[5] = Wk2; p8.d[5] = tk2;
    p8.s[6] = Wv2; p8.d[6] = tv2;  p8.s[7] = Wo2; p8.d[7] = to2;
    transpose8<<<dim3(CC/32, CC/32, 8), tblk>>>(p8);
    transpose_k<<<dim3(FF/32, CC/32), tblk>>>(Wf1, tf1, CC, FF);
    transpose_k<<<dim3(CC/32, FF/32), tblk>>>(Wf2, tf2, FF, CC);

    const dim3 gQKV(3072/128, MM/128);   // (24, 32) fused self QKV
    const dim3 gKV (2048/128, MM/128);   // (16, 32) fused cross KV
    const dim3 gP  (CC/128,   MM/128);   // (8, 32)
    const dim3 gF1 (FF/128,   MM/128);   // (32, 32)
    const dim3 gFl (TT/128, BB*HH);      // (8, 64)
    const dim3 gVt (CC/32, TT/32, BB);
    const int nLn = MM;

    // ---- self-attention (causal) ----
    kProj<<<gQKV, blk, GSMEM>>>(gxr, tq1, nullptr, gff, CC, CC, CC, 3072);
    transpose_v<<<gVt, tblk>>>(gff + 2048, gvt, 3072);
    flash_k<true><<<gFl, blk, FSMEM>>>(gff, gff + 1024, gvt, tmask, gctx, 3072, 3072);
    kProj<<<gP, blk, GSMEM>>>(gctx, to1, nullptr, go, CC, CC, CC, CC);
    add_ln<true><<<nLn, blk>>>(x, go, ln1g, ln1b, gx1);

    // ---- cross-attention ----
    kProjR<<<gP,  blk, GSMEM>>>(gx1, tq2, nullptr, gq, CC, CC, CC, CC);
    kProj <<<gKV, blk, GSMEM>>>(ger, tk2, nullptr, gff, CC, CC, CC, 2048);
    transpose_v<<<gVt, tblk>>>(gff + 1024, gvt, 2048);
    flash_k<false><<<gFl, blk, FSMEM>>>(gq, gff, gvt, smask, gctx, CC, 2048);
    kProj<<<gP, blk, GSMEM>>>(gctx, to2, nullptr, go, CC, CC, CC, CC);
    add_ln<true><<<nLn, blk>>>(gx1, go, ln2g, ln2b, gx2);

    // ---- FFN ----
    kFfn1<<<gF1, blk, GSMEM>>>(gx2, tf1, bf1, gff, CC, CC, CC, FF);
    kFfn2<<<gP,  blk, GSMEM>>>(gff, tf2, bf2, go, FF, FF, FF, CC);
    add_ln<false><<<nLn, blk>>>(gx2, go, ln3g, ln3b, out);
}